// round 8
// baseline (speedup 1.0000x reference)
#include <cuda_runtime.h>

#define BB   4
#define SS   1024
#define HIDN 768
#define HH   12
#define DD   64

// Scratch (no cudaMalloc allowed): Q/K/V in [B,H,S,D] layout, fp32.
__device__ float g_Q[BB*HH*SS*DD];
__device__ float g_K[BB*HH*SS*DD];
__device__ float g_V[BB*HH*SS*DD];

// ---- packed fp32x2 helpers (FFMA2 path; bit-exact fp32 per lane) ----------
__device__ __forceinline__ void ffma2(unsigned long long& d,
                                      unsigned long long a,
                                      unsigned long long b) {
    asm("fma.rn.f32x2 %0, %1, %2, %0;" : "+l"(d) : "l"(a), "l"(b));
}
__device__ __forceinline__ unsigned long long pack2(float x, float y) {
    unsigned long long r;
    asm("mov.b64 %0, {%1, %2};" : "=l"(r) : "f"(x), "f"(y));
    return r;
}
__device__ __forceinline__ float2 unpack2(unsigned long long v) {
    float2 r;
    asm("mov.b64 {%0, %1}, %2;" : "=f"(r.x), "=f"(r.y) : "l"(v));
    return r;
}

// ---------------------------------------------------------------------------
// Kernel 1: QKV projection (unchanged from R7: ~73% of FFMA2 floor).
// ---------------------------------------------------------------------------
__global__ __launch_bounds__(256) void qkv_proj(
    const float* __restrict__ X,
    const float* __restrict__ Wq, const float* __restrict__ bq,
    const float* __restrict__ Wk, const float* __restrict__ bk,
    const float* __restrict__ Wv, const float* __restrict__ bv)
{
    __shared__ float As[16][132];   // transposed: As[k][m], padded
    __shared__ float Bs[16][64];    // Bs[k][n]

    const float* W; const float* bias; float* out;
    if      (blockIdx.z == 0) { W = Wq; bias = bq; out = g_Q; }
    else if (blockIdx.z == 1) { W = Wk; bias = bk; out = g_K; }
    else                      { W = Wv; bias = bv; out = g_V; }

    const int tid     = threadIdx.x;
    const int rowBase = blockIdx.y * 128;
    const int head    = blockIdx.x;
    const int colBase = head * 64;

    const int m0 = (tid >> 4) * 8;
    const int n0 = (tid & 15) * 4;

    unsigned long long acc2[4][4];   // [n][m-pair]
    #pragma unroll
    for (int j = 0; j < 4; j++)
        #pragma unroll
        for (int p = 0; p < 4; p++) acc2[j][p] = 0ull;

    for (int kt = 0; kt < 48; kt++) {
        #pragma unroll
        for (int i = 0; i < 2; i++) {
            int f  = tid + i * 256;
            int r  = f >> 2;
            int kk = (f & 3) * 4;
            float4 v = *(const float4*)&X[(size_t)(rowBase + r) * HIDN + kt * 16 + kk];
            As[kk + 0][r] = v.x; As[kk + 1][r] = v.y;
            As[kk + 2][r] = v.z; As[kk + 3][r] = v.w;
        }
        {
            int k  = tid >> 4;
            int nn = (tid & 15) * 4;
            float4 v = *(const float4*)&W[(size_t)(kt * 16 + k) * HIDN + colBase + nn];
            *(float4*)&Bs[k][nn] = v;
        }
        __syncthreads();

        #pragma unroll
        for (int k = 0; k < 16; k++) {
            ulonglong2 a01 = *(const ulonglong2*)&As[k][m0];
            ulonglong2 a23 = *(const ulonglong2*)&As[k][m0 + 4];
            float4 bb = *(const float4*)&Bs[k][n0];
            unsigned long long bp[4];
            bp[0] = pack2(bb.x, bb.x); bp[1] = pack2(bb.y, bb.y);
            bp[2] = pack2(bb.z, bb.z); bp[3] = pack2(bb.w, bb.w);
            #pragma unroll
            for (int j = 0; j < 4; j++) {
                ffma2(acc2[j][0], a01.x, bp[j]);
                ffma2(acc2[j][1], a01.y, bp[j]);
                ffma2(acc2[j][2], a23.x, bp[j]);
                ffma2(acc2[j][3], a23.y, bp[j]);
            }
        }
        __syncthreads();
    }

    float accf[8][4];
    #pragma unroll
    for (int j = 0; j < 4; j++)
        #pragma unroll
        for (int p = 0; p < 4; p++) {
            float2 v = unpack2(acc2[j][p]);
            accf[2 * p + 0][j] = v.x;
            accf[2 * p + 1][j] = v.y;
        }

    float bl[4];
    #pragma unroll
    for (int j = 0; j < 4; j++) bl[j] = bias[colBase + n0 + j];

    #pragma unroll
    for (int i = 0; i < 8; i++) {
        int r = rowBase + m0 + i;
        int b = r >> 10;
        int s = r & 1023;
        float4 o;
        o.x = accf[i][0] + bl[0]; o.y = accf[i][1] + bl[1];
        o.z = accf[i][2] + bl[2]; o.w = accf[i][3] + bl[3];
        *(float4*)&out[(((size_t)b * HH + head) * SS + s) * DD + n0] = o;
    }
}

// ---------------------------------------------------------------------------
// Kernel 2: fused dual-softmax gated attention.
// R8 changes vs R7 (L1=74.9% wavefront-bound):
//  * Q held in 32 b64 REGISTERS for all of phase 1 (one-time smem read;
//    removes ~16k in-loop Q wavefronts/CTA).
//  * softmax pass A fused into phase-1 epilogue: bufT stores e_g directly,
//    Z_g/Z_l accumulate as per-lane register partials across chunks
//    (removes a full bufT read+write sweep, ~3k wf/CTA).
// smem layout identical to R7 (qs2 kept: Q stage + phase-3 scratch).
// ---------------------------------------------------------------------------
#define OFF_BUF  0
#define OFF_KS   32768
#define OFF_QS   40960
#define OFF_AMS  43072
#define OFF_EAM  44096
#define OFF_GS   45120
#define OFF_REDA 45152
#define OFF_REDB 45664
#define OFF_CG   46176
#define OFF_CL   46208
#define OFF_MB   46240
#define ATTN_SMEM_BYTES ((46240 + 1024) * 4)

__global__ __launch_bounds__(512) void attn_kernel(
    const float* __restrict__ am,     // [B,1,1,S]
    const int*   __restrict__ lm,     // [B,1,S,S]
    const float* __restrict__ gate,   // [B,H,S,1]
    float* __restrict__ out)          // [B,S,HID]
{
    extern __shared__ float smf[];
    float*    bufT   = smf + OFF_BUF;     // [1024][32] e_g^T -> weights^T
    float*    ks     = smf + OFF_KS;      // [128][64] K/V chunk, natural
    float*    qs2    = smf + OFF_QS;      // [32][66] Q stage / ph3 scratch
    float*    ams    = smf + OFF_AMS;
    float*    eam    = smf + OFF_EAM;
    float*    gs     = smf + OFF_GS;
    float*    redA   = smf + OFF_REDA;
    float*    redB   = smf + OFF_REDB;
    float*    cgF    = smf + OFF_CG;
    float*    clF    = smf + OFF_CL;
    unsigned* mbitsT = (unsigned*)(smf + OFF_MB);

    const int tid   = threadIdx.x;
    const int lane  = tid & 31;          // == q row
    const int warp  = tid >> 5;          // 0..15
    const int qtile = blockIdx.x;
    const int h     = blockIdx.y;
    const int b     = blockIdx.z;
    const int qbase = qtile * 32;
    const size_t bh = (size_t)b * HH + h;
    const float* Qp = g_Q + bh * SS * DD;
    const float* Kp = g_K + bh * SS * DD;
    const float* Vp = g_V + bh * SS * DD;

    // ---- one-time staging ----
    #pragma unroll
    for (int i = 0; i < 4; i++) {
        int idx = tid + i * 512;              // 0..2047
        int q = idx >> 6, d = idx & 63;
        qs2[q * 66 + d] = Qp[(size_t)(qbase + q) * DD + d];
    }
    if (tid < 256) {
        float4 v = *(const float4*)&am[(size_t)b * SS + tid * 4];
        *(float4*)&ams[tid * 4] = v;
    }
    if (tid < 32) gs[tid] = gate[bh * SS + qbase + tid];

    // local mask -> 1 bit, mbitsT[kword][q]; each warp owns 2 q rows
    #pragma unroll
    for (int i = 0; i < 2; i++) {
        int q = warp * 2 + i;
        const int* mrow = lm + ((size_t)b * SS + (qbase + q)) * SS;
        for (int kw = 0; kw < 32; kw++) {
            int v = mrow[kw * 32 + lane];
            unsigned bal = __ballot_sync(0xffffffffu, v != 0);
            if (lane == 0) mbitsT[kw * 32 + q] = bal;
        }
    }
    __syncthreads();                          // qs2/ams ready
    #pragma unroll
    for (int i = 0; i < 2; i++) {
        int k = tid + i * 512;
        eam[k] = __expf(-ams[k]);
    }

    // ---- Q row -> registers (one-time; 8B LDS, 2-way conflict, ~32 instr) ----
    unsigned long long qreg[32];              // qreg[j] = (d=2j, d=2j+1)
    #pragma unroll
    for (int j = 0; j < 32; j++)
        qreg[j] = *(const unsigned long long*)&qs2[lane * 66 + 2 * j];

    // ---- phase 1: e_g^T = exp(QK^T/8 + am), Z partials in registers ----
    // warp owns 8 k-cols per 128-k chunk; K broadcast from natural ks[k][d].
    const int k0      = warp * 8;
    const int bitbase = k0 & 31;              // 8*warp mod 32
    float zg = 0.f, zl = 0.f;
    for (int c = 0; c < 8; c++) {
        __syncthreads();                      // eam (c==0) + ks reuse ordering
        #pragma unroll
        for (int i = 0; i < 4; i++) {         // stage 128x64 K chunk
            int f  = tid + i * 512;
            int kr = f >> 4;
            int d4 = (f & 15) << 2;
            float4 v = *(const float4*)&Kp[(size_t)(c * 128 + kr) * DD + d4];
            *(float4*)&ks[kr * 64 + d4] = v;
        }
        __syncthreads();

        unsigned long long acc2[8];
        #pragma unroll
        for (int t = 0; t < 8; t++) acc2[t] = 0ull;

        #pragma unroll 4
        for (int s = 0; s < 16; s++) {        // d = 4*s
            unsigned long long qp0 = qreg[2 * s];
            unsigned long long qp1 = qreg[2 * s + 1];
            #pragma unroll
            for (int t = 0; t < 8; t++) {
                ulonglong2 kv = *(const ulonglong2*)&ks[(k0 + t) * 64 + 4 * s]; // broadcast
                ffma2(acc2[t], qp0, kv.x);
                ffma2(acc2[t], qp1, kv.y);
            }
        }

        // epilogue: exp + Z partials (fused pass A)
        unsigned mw = mbitsT[(c * 4 + (warp >> 2)) * 32 + lane];
        #pragma unroll
        for (int t = 0; t < 8; t++) {
            int k = c * 128 + k0 + t;
            float2 v = unpack2(acc2[t]);
            float s  = (v.x + v.y) * 0.125f;
            float eg = __expf(s + ams[k]);
            bufT[(size_t)k * 32 + lane] = eg;
            zg += eg;
            if ((mw >> (bitbase + t)) & 1u) zl += eg * eam[k];
        }
    }

    // ---- phase 2 remnant: Z reduction + gate coefficients + pass B ----
    redA[warp * 32 + lane] = zg;
    redB[warp * 32 + lane] = zl;
    __syncthreads();
    if (tid < 32) {
        float a = 0.f, bb2 = 0.f;
        #pragma unroll
        for (int i = 0; i < 16; i++) {
            a   += redA[i * 32 + tid];
            bb2 += redB[i * 32 + tid];
        }
        float g = gs[tid];
        cgF[tid] = (1.f - g) / a;     // global coeff / Z_g
        clF[tid] = g / bb2;           // local  coeff / Z_l
    }
    __syncthreads();
    {   // pass B: w = e_g * (cg + mask * cl * eam[k]); warp owns 64 k
        const int kw0 = warp * 64;
        float cg = cgF[lane], cl = clF[lane];
        #pragma unroll
        for (int kk = 0; kk < 64; kk += 32) {
            unsigned mw = mbitsT[((kw0 + kk) >> 5) * 32 + lane];
            #pragma unroll
            for (int j = 0; j < 32; j++) {
                int k = kw0 + kk + j;
                float eg = bufT[(size_t)k * 32 + lane];
                float f  = ((mw >> j) & 1u) ? fmaf(cl, eam[k], cg) : cg;
                bufT[(size_t)k * 32 + lane] = eg * f;
            }
        }
    }

    // ---- phase 3: ctx = W @ V ----
    // warp (w&7) owns 8 d-cols (4 FFMA2 pairs); warp>>3 picks k-half.
    {
        const int d0    = (warp & 7) * 8;
        const int kbase = (warp >> 3) * 64;
        unsigned long long cacc2[4] = {0ull, 0ull, 0ull, 0ull};

        for (int c = 0; c < 8; c++) {
            __syncthreads();                  // pass-B writes (c==0) + ks reuse
            #pragma unroll
            for (int i = 0; i < 4; i++) {     // stage 128x64 V chunk
                int f  = tid + i * 512;
                int kr = f >> 4;
                int d4 = (f & 15) << 2;
                float4 v = *(const float4*)&Vp[(size_t)(c * 128 + kr) * DD + d4];
                *(float4*)&ks[kr * 64 + d4] = v;
            }
            __syncthreads();

            #pragma unroll 4
            for (int kk = 0; kk < 64; kk++) {
                int k = kbase + kk;
                float wv = bufT[(size_t)(c * 128 + k) * 32 + lane];
                unsigned long long wp = pack2(wv, wv);
                ulonglong2 v0 = *(const ulonglong2*)&ks[k * 64 + d0];     // broadcast
                ulonglong2 v1 = *(const ulonglong2*)&ks[k * 64 + d0 + 4]; // broadcast
                ffma2(cacc2[0], wp, v0.x);
                ffma2(cacc2[1], wp, v0.y);
                ffma2(cacc2[2], wp, v1.x);
                ffma2(cacc2[3], wp, v1.y);
            }
        }

        float cacc[8];
        #pragma unroll
        for (int p = 0; p < 4; p++) {
            float2 v = unpack2(cacc2[p]);
            cacc[2 * p + 0] = v.x;
            cacc[2 * p + 1] = v.y;
        }

        // reduce the two k-halves: warps 8..15 park partials in qs2 scratch
        if (warp >= 8) {
            #pragma unroll
            for (int j = 0; j < 8; j++)
                qs2[(warp - 8) * 256 + j * 32 + lane] = cacc[j];
        }
        __syncthreads();
        if (warp < 8) {
            #pragma unroll
            for (int j = 0; j < 8; j++)
                cacc[j] += qs2[warp * 256 + j * 32 + lane];

            int s = qbase + lane;
            size_t o = ((size_t)b * SS + s) * HIDN + h * DD + d0;
            float4 o0 = {cacc[0], cacc[1], cacc[2], cacc[3]};
            float4 o1 = {cacc[4], cacc[5], cacc[6], cacc[7]};
            *(float4*)&out[o]     = o0;
            *(float4*)&out[o + 4] = o1;
        }
    }
}

// ---------------------------------------------------------------------------
// Launch: two kernels on the capture stream. No sync, no allocation.
// ---------------------------------------------------------------------------
extern "C" void kernel_launch(void* const* d_in, const int* in_sizes, int n_in,
                              void* d_out, int out_size)
{
    const float* hs   = (const float*)d_in[0];
    const float* am   = (const float*)d_in[1];
    const int*   lmsk = (const int*)  d_in[2];
    const float* gate = (const float*)d_in[3];
    const float* Wq   = (const float*)d_in[4];
    const float* bq   = (const float*)d_in[5];
    const float* Wk   = (const float*)d_in[6];
    const float* bk   = (const float*)d_in[7];
    const float* Wv   = (const float*)d_in[8];
    const float* bv   = (const float*)d_in[9];
    float* out = (float*)d_out;

    cudaFuncSetAttribute(attn_kernel,
                         cudaFuncAttributeMaxDynamicSharedMemorySize,
                         ATTN_SMEM_BYTES);

    dim3 gp(12, 32, 3);                 // heads x row-blocks x {Q,K,V}
    qkv_proj<<<gp, 256>>>(hs, Wq, bq, Wk, bk, Wv, bv);

    dim3 ga(32, 12, 4);                 // q-tiles x heads x batch
    attn_kernel<<<ga, 512, ATTN_SMEM_BYTES>>>(am, lmsk, gate, out);
}

// round 14
// speedup vs baseline: 1.2973x; 1.2973x over previous
#include <cuda_runtime.h>
#include <cstdint>

#define BB   4
#define SS   1024
#define HIDN 768
#define HH   12
#define DD   64

// Scratch (no cudaMalloc allowed): Q/K/V in [B,H,S,D] layout, fp32.
__device__ float g_Q[BB*HH*SS*DD];
__device__ float g_K[BB*HH*SS*DD];
__device__ float g_V[BB*HH*SS*DD];

// ---- packed fp32x2 helpers (FFMA2 path; bit-exact fp32 per lane) ----------
__device__ __forceinline__ void ffma2(unsigned long long& d,
                                      unsigned long long a,
                                      unsigned long long b) {
    asm("fma.rn.f32x2 %0, %1, %2, %0;" : "+l"(d) : "l"(a), "l"(b));
}
__device__ __forceinline__ unsigned long long pack2(float x, float y) {
    unsigned long long r;
    asm("mov.b64 %0, {%1, %2};" : "=l"(r) : "f"(x), "f"(y));
    return r;
}
__device__ __forceinline__ float2 unpack2(unsigned long long v) {
    float2 r;
    asm("mov.b64 {%0, %1}, %2;" : "=f"(r.x), "=f"(r.y) : "l"(v));
    return r;
}

// ---- mma.sync tf32 helpers (sm_80+ standard PTX; valid on sm_100) ----------
// NOTE: cvt with .tf32 destination requires a .b32 register operand ("=r"),
// not .f32 ("=f") — that mismatch was R13's compile failure.
__device__ __forceinline__ float to_tf32(float x) {
    uint32_t r;
    asm("cvt.rna.tf32.f32 %0, %1;" : "=r"(r) : "f"(x));
    return __uint_as_float(r);
}
__device__ __forceinline__ void mma_tf32(float* d, const uint32_t* a,
                                         const uint32_t* b) {
    asm volatile(
        "mma.sync.aligned.m16n8k8.row.col.f32.tf32.tf32.f32 "
        "{%0,%1,%2,%3}, {%4,%5,%6,%7}, {%8,%9}, {%0,%1,%2,%3};"
        : "+f"(d[0]), "+f"(d[1]), "+f"(d[2]), "+f"(d[3])
        : "r"(a[0]), "r"(a[1]), "r"(a[2]), "r"(a[3]), "r"(b[0]), "r"(b[1]));
}

// ---------------------------------------------------------------------------
// Kernel 1a: QKV projection via mma.sync tf32 (HMMA).
// Grid (12 heads, 32 mtiles, 3 qkv), 256 threads = 8 warps in 4(M)x2(N).
// BM=128, BN=64, BK=32; warp tile 32x32 = 2 m16 x 4 n8 x 4 k8 steps.
// Inputs tf32-rounded (cvt.rna) at staging. Pads 36/68 -> fragment loads
// conflict-free (4g+tig / 4tig+g bijective mod 32).
// Fragment layout per PTX ISA (audited): A a0..a3 = [g][tig],[g+8][tig],
// [g][tig+4],[g+8][tig+4]; B b0,b1 = [tig][g],[tig+4][g]; C c0..c3 =
// (g,2tig),(g,2tig+1),(g+8,2tig),(g+8,2tig+1).
// Verified post-hoc by qkv_fix (fallback to proven FFMA2 SIMT tile).
// ---------------------------------------------------------------------------
__global__ __launch_bounds__(256) void qkv_mma(
    const float* __restrict__ X,
    const float* __restrict__ Wq, const float* __restrict__ bq,
    const float* __restrict__ Wk, const float* __restrict__ bk,
    const float* __restrict__ Wv, const float* __restrict__ bv)
{
    __shared__ float As[128][36];   // [m][k], pad 36
    __shared__ float Bs[32][68];    // [k][n], pad 68

    const float* W; const float* bias; float* out;
    if      (blockIdx.z == 0) { W = Wq; bias = bq; out = g_Q; }
    else if (blockIdx.z == 1) { W = Wk; bias = bk; out = g_K; }
    else                      { W = Wv; bias = bv; out = g_V; }

    const int tid     = threadIdx.x;
    const int wid     = tid >> 5;
    const int lane    = tid & 31;
    const int g       = lane >> 2;        // groupID 0..7
    const int tig     = lane & 3;         // thread-in-group 0..3
    const int wm      = (wid & 3) * 32;   // warp m offset
    const int wn      = (wid >> 2) * 32;  // warp n offset (0/32)
    const int head    = blockIdx.x;
    const int mbase   = blockIdx.y * 128;
    const int colBase = head * 64;

    float acc[2][4][4];
    #pragma unroll
    for (int mt = 0; mt < 2; mt++)
        #pragma unroll
        for (int nt = 0; nt < 4; nt++)
            #pragma unroll
            for (int r = 0; r < 4; r++) acc[mt][nt][r] = 0.f;

    for (int c = 0; c < 24; c++) {
        __syncthreads();
        // stage A [128m][32k], tf32-rounded
        #pragma unroll
        for (int i = 0; i < 4; i++) {
            int f  = tid + i * 256;           // 0..1023 float4
            int m  = f >> 3;
            int k4 = (f & 7) * 4;
            float4 v = *(const float4*)&X[(size_t)(mbase + m) * HIDN + c * 32 + k4];
            v.x = to_tf32(v.x); v.y = to_tf32(v.y);
            v.z = to_tf32(v.z); v.w = to_tf32(v.w);
            *(float4*)&As[m][k4] = v;
        }
        // stage B [32k][64n], tf32-rounded
        #pragma unroll
        for (int i = 0; i < 2; i++) {
            int f  = tid + i * 256;           // 0..511 float4
            int k  = f >> 4;
            int n4 = (f & 15) * 4;
            float4 v = *(const float4*)&W[(size_t)(c * 32 + k) * HIDN + colBase + n4];
            v.x = to_tf32(v.x); v.y = to_tf32(v.y);
            v.z = to_tf32(v.z); v.w = to_tf32(v.w);
            *(float4*)&Bs[k][n4] = v;
        }
        __syncthreads();

        #pragma unroll
        for (int ks = 0; ks < 4; ks++) {
            uint32_t a[2][4], b[4][2];
            #pragma unroll
            for (int mt = 0; mt < 2; mt++) {
                int r0 = wm + mt * 16 + g;
                a[mt][0] = __float_as_uint(As[r0    ][ks * 8 + tig]);
                a[mt][1] = __float_as_uint(As[r0 + 8][ks * 8 + tig]);
                a[mt][2] = __float_as_uint(As[r0    ][ks * 8 + tig + 4]);
                a[mt][3] = __float_as_uint(As[r0 + 8][ks * 8 + tig + 4]);
            }
            #pragma unroll
            for (int nt = 0; nt < 4; nt++) {
                int n = wn + nt * 8 + g;
                b[nt][0] = __float_as_uint(Bs[ks * 8 + tig    ][n]);
                b[nt][1] = __float_as_uint(Bs[ks * 8 + tig + 4][n]);
            }
            #pragma unroll
            for (int mt = 0; mt < 2; mt++)
                #pragma unroll
                for (int nt = 0; nt < 4; nt++)
                    mma_tf32(acc[mt][nt], a[mt], b[nt]);
        }
    }

    // epilogue: c0/c1 = row g cols 2tig/2tig+1; c2/c3 = row g+8
    #pragma unroll
    for (int mt = 0; mt < 2; mt++)
        #pragma unroll
        for (int rr = 0; rr < 2; rr++) {
            int m  = mbase + wm + mt * 16 + g + rr * 8;
            int bb = m >> 10, sr = m & 1023;
            #pragma unroll
            for (int nt = 0; nt < 4; nt++) {
                int d = wn + nt * 8 + 2 * tig;
                float2 o;
                o.x = acc[mt][nt][rr * 2 + 0] + bias[colBase + d];
                o.y = acc[mt][nt][rr * 2 + 1] + bias[colBase + d + 1];
                *(float2*)&out[(((size_t)bb * HH + head) * SS + sr) * DD + d] = o;
            }
        }
}

// ---------------------------------------------------------------------------
// Kernel 1b: verify-and-fix. Grid (12 heads, 32 mtiles, 3 qkv), 256 threads.
// Each CTA checks 3 scattered elements of ITS tile against fp32 dot products
// (tol 0.05 >> tf32 err ~2e-4, << layout-bug garbage O(0.7)). Clean -> exit.
// Dirty -> recompute tile with the proven R7 FFMA2 SIMT GEMM. Deterministic.
// ---------------------------------------------------------------------------
__global__ __launch_bounds__(256) void qkv_fix(
    const float* __restrict__ X,
    const float* __restrict__ Wq, const float* __restrict__ bq,
    const float* __restrict__ Wk, const float* __restrict__ bk,
    const float* __restrict__ Wv, const float* __restrict__ bv)
{
    __shared__ float As[16][132];
    __shared__ float Bs[16][64];
    __shared__ float red[24];
    __shared__ int   bad;

    const float* W; const float* bias; float* out;
    if      (blockIdx.z == 0) { W = Wq; bias = bq; out = g_Q; }
    else if (blockIdx.z == 1) { W = Wk; bias = bk; out = g_K; }
    else                      { W = Wv; bias = bv; out = g_V; }

    const int tid     = threadIdx.x;
    const int lane    = tid & 31;
    const int wid     = tid >> 5;
    const int rowBase = blockIdx.y * 128;
    const int head    = blockIdx.x;
    const int colBase = head * 64;

    const int mo[3] = {5, 67, 121};
    const int no[3] = {1, 29, 62};
    #pragma unroll
    for (int s = 0; s < 3; s++) {
        int gm = rowBase + mo[s];
        int n  = colBase + no[s];
        float p = 0.f;
        for (int kk = tid; kk < HIDN; kk += 256)
            p += X[(size_t)gm * HIDN + kk] * W[(size_t)kk * HIDN + n];
        #pragma unroll
        for (int o = 16; o; o >>= 1) p += __shfl_xor_sync(0xffffffffu, p, o);
        if (lane == 0) red[s * 8 + wid] = p;
    }
    if (tid == 0) bad = 0;
    __syncthreads();
    if (tid == 0) {
        int isbad = 0;
        #pragma unroll
        for (int s = 0; s < 3; s++) {
            float ref = bias[colBase + no[s]];
            #pragma unroll
            for (int w = 0; w < 8; w++) ref += red[s * 8 + w];
            int gm = rowBase + mo[s];
            int bb = gm >> 10, sr = gm & 1023;
            float got = out[(((size_t)bb * HH + head) * SS + sr) * DD + no[s]];
            if (!(fabsf(got - ref) < 0.05f)) isbad = 1;  // catches NaN too
        }
        bad = isbad;
    }
    __syncthreads();
    if (!bad) return;

    // fallback: R7 FFMA2 SIMT tile GEMM
    const int m0 = (tid >> 4) * 8;
    const int n0 = (tid & 15) * 4;

    unsigned long long acc2[4][4];
    #pragma unroll
    for (int j = 0; j < 4; j++)
        #pragma unroll
        for (int p = 0; p < 4; p++) acc2[j][p] = 0ull;

    for (int kt = 0; kt < 48; kt++) {
        #pragma unroll
        for (int i = 0; i < 2; i++) {
            int f  = tid + i * 256;
            int r  = f >> 2;
            int kk = (f & 3) * 4;
            float4 v = *(const float4*)&X[(size_t)(rowBase + r) * HIDN + kt * 16 + kk];
            As[kk + 0][r] = v.x; As[kk + 1][r] = v.y;
            As[kk + 2][r] = v.z; As[kk + 3][r] = v.w;
        }
        {
            int k  = tid >> 4;
            int nn = (tid & 15) * 4;
            float4 v = *(const float4*)&W[(size_t)(kt * 16 + k) * HIDN + colBase + nn];
            *(float4*)&Bs[k][nn] = v;
        }
        __syncthreads();

        #pragma unroll
        for (int k = 0; k < 16; k++) {
            ulonglong2 a01 = *(const ulonglong2*)&As[k][m0];
            ulonglong2 a23 = *(const ulonglong2*)&As[k][m0 + 4];
            float4 bb = *(const float4*)&Bs[k][n0];
            unsigned long long bp[4];
            bp[0] = pack2(bb.x, bb.x); bp[1] = pack2(bb.y, bb.y);
            bp[2] = pack2(bb.z, bb.z); bp[3] = pack2(bb.w, bb.w);
            #pragma unroll
            for (int j = 0; j < 4; j++) {
                ffma2(acc2[j][0], a01.x, bp[j]);
                ffma2(acc2[j][1], a01.y, bp[j]);
                ffma2(acc2[j][2], a23.x, bp[j]);
                ffma2(acc2[j][3], a23.y, bp[j]);
            }
        }
        __syncthreads();
    }

    float accf[8][4];
    #pragma unroll
    for (int j = 0; j < 4; j++)
        #pragma unroll
        for (int p = 0; p < 4; p++) {
            float2 v = unpack2(acc2[j][p]);
            accf[2 * p + 0][j] = v.x;
            accf[2 * p + 1][j] = v.y;
        }

    float bl[4];
    #pragma unroll
    for (int j = 0; j < 4; j++) bl[j] = bias[colBase + n0 + j];

    #pragma unroll
    for (int i = 0; i < 8; i++) {
        int r = rowBase + m0 + i;
        int b = r >> 10;
        int s = r & 1023;
        float4 o;
        o.x = accf[i][0] + bl[0]; o.y = accf[i][1] + bl[1];
        o.z = accf[i][2] + bl[2]; o.w = accf[i][3] + bl[3];
        *(float4*)&out[(((size_t)b * HH + head) * SS + s) * DD + n0] = o;
    }
}

// ---------------------------------------------------------------------------
// Kernel 2: fused dual-softmax gated attention (R9: Q pairs from qs2 in-loop
// as in the 1032us R7 version; fused pass-A; register-prefetch double
// buffering of K/V chunk staging to hide gmem latency).
// ---------------------------------------------------------------------------
#define OFF_BUF  0
#define OFF_KS   32768
#define OFF_QS   40960
#define OFF_AMS  43072
#define OFF_EAM  44096
#define OFF_GS   45120
#define OFF_REDA 45152
#define OFF_REDB 45664
#define OFF_CG   46176
#define OFF_CL   46208
#define OFF_MB   46240
#define ATTN_SMEM_BYTES ((46240 + 1024) * 4)

__global__ __launch_bounds__(512) void attn_kernel(
    const float* __restrict__ am,     // [B,1,1,S]
    const int*   __restrict__ lm,     // [B,1,S,S]
    const float* __restrict__ gate,   // [B,H,S,1]
    float* __restrict__ out)          // [B,S,HID]
{
    extern __shared__ float smf[];
    float*    bufT   = smf + OFF_BUF;     // [1024][32] e_g^T -> weights^T
    float*    ks     = smf + OFF_KS;      // [128][64] K/V chunk, natural
    float*    qs2    = smf + OFF_QS;      // [32][66] Q stage / ph3 scratch
    float*    ams    = smf + OFF_AMS;
    float*    eam    = smf + OFF_EAM;
    float*    gs     = smf + OFF_GS;
    float*    redA   = smf + OFF_REDA;
    float*    redB   = smf + OFF_REDB;
    float*    cgF    = smf + OFF_CG;
    float*    clF    = smf + OFF_CL;
    unsigned* mbitsT = (unsigned*)(smf + OFF_MB);

    const int tid   = threadIdx.x;
    const int lane  = tid & 31;          // == q row
    const int warp  = tid >> 5;          // 0..15
    const int qtile = blockIdx.x;
    const int h     = blockIdx.y;
    const int b     = blockIdx.z;
    const int qbase = qtile * 32;
    const size_t bh = (size_t)b * HH + h;
    const float* Qp = g_Q + bh * SS * DD;
    const float* Kp = g_K + bh * SS * DD;
    const float* Vp = g_V + bh * SS * DD;

    // ---- one-time staging ----
    #pragma unroll
    for (int i = 0; i < 4; i++) {
        int idx = tid + i * 512;              // 0..2047
        int q = idx >> 6, d = idx & 63;
        qs2[q * 66 + d] = Qp[(size_t)(qbase + q) * DD + d];
    }
    if (tid < 256) {
        float4 v = *(const float4*)&am[(size_t)b * SS + tid * 4];
        *(float4*)&ams[tid * 4] = v;
    }
    if (tid < 32) gs[tid] = gate[bh * SS + qbase + tid];

    #pragma unroll
    for (int i = 0; i < 2; i++) {
        int q = warp * 2 + i;
        const int* mrow = lm + ((size_t)b * SS + (qbase + q)) * SS;
        for (int kw = 0; kw < 32; kw++) {
            int v = mrow[kw * 32 + lane];
            unsigned bal = __ballot_sync(0xffffffffu, v != 0);
            if (lane == 0) mbitsT[kw * 32 + q] = bal;
        }
    }
    __syncthreads();                          // qs2/ams ready
    #pragma unroll
    for (int i = 0; i < 2; i++) {
        int k = tid + i * 512;
        eam[k] = __expf(-ams[k]);
    }

    // ---- phase 1: e_g^T = exp(QK^T/8 + am), Z partials in registers ----
    const int k0      = warp * 8;
    const int bitbase = k0 & 31;
    float zg = 0.f, zl = 0.f;
    {
        float4 kbuf[4];
        #pragma unroll
        for (int i = 0; i < 4; i++) {          // prefetch chunk 0
            int f = tid + i * 512;
            kbuf[i] = *(const float4*)&Kp[(size_t)(f >> 4) * DD + ((f & 15) << 2)];
        }
        for (int c = 0; c < 8; c++) {
            __syncthreads();                   // eam (c==0) / prev compute done
            #pragma unroll
            for (int i = 0; i < 4; i++) {
                int f = tid + i * 512;
                *(float4*)&ks[(f >> 4) * 64 + ((f & 15) << 2)] = kbuf[i];
            }
            __syncthreads();
            if (c < 7) {
                #pragma unroll
                for (int i = 0; i < 4; i++) {  // prefetch next (overlaps compute)
                    int f = tid + i * 512;
                    kbuf[i] = *(const float4*)&Kp[(size_t)((c + 1) * 128 + (f >> 4)) * DD
                                                  + ((f & 15) << 2)];
                }
            }

            unsigned long long acc2[8];
            #pragma unroll
            for (int t = 0; t < 8; t++) acc2[t] = 0ull;

            #pragma unroll 4
            for (int s = 0; s < 16; s++) {     // d = 4*s
                unsigned long long qp0 = *(const unsigned long long*)&qs2[lane * 66 + 4 * s];
                unsigned long long qp1 = *(const unsigned long long*)&qs2[lane * 66 + 4 * s + 2];
                #pragma unroll
                for (int t = 0; t < 8; t++) {
                    ulonglong2 kv = *(const ulonglong2*)&ks[(k0 + t) * 64 + 4 * s];
                    ffma2(acc2[t], qp0, kv.x);
                    ffma2(acc2[t], qp1, kv.y);
                }
            }

            unsigned mw = mbitsT[(c * 4 + (warp >> 2)) * 32 + lane];
            #pragma unroll
            for (int t = 0; t < 8; t++) {
                int k = c * 128 + k0 + t;
                float2 v = unpack2(acc2[t]);
                float s  = (v.x + v.y) * 0.125f;
                float eg = __expf(s + ams[k]);
                bufT[(size_t)k * 32 + lane] = eg;
                zg += eg;
                if ((mw >> (bitbase + t)) & 1u) zl += eg * eam[k];
            }
        }
    }

    // ---- Z reduction + gate coefficients + pass B ----
    redA[warp * 32 + lane] = zg;
    redB[warp * 32 + lane] = zl;
    __syncthreads();
    if (tid < 32) {
        float a = 0.f, bb2 = 0.f;
        #pragma unroll
        for (int i = 0; i < 16; i++) {
            a   += redA[i * 32 + tid];
            bb2 += redB[i * 32 + tid];
        }
        float g = gs[tid];
        cgF[tid] = (1.f - g) / a;
        clF[tid] = g / bb2;
    }
    __syncthreads();
    {
        const int kw0 = warp * 64;
        float cg = cgF[lane], cl = clF[lane];
        #pragma unroll
        for (int kk = 0; kk < 64; kk += 32) {
            unsigned mw = mbitsT[((kw0 + kk) >> 5) * 32 + lane];
            #pragma unroll
            for (int j = 0; j < 32; j++) {
                int k = kw0 + kk + j;
                float eg = bufT[(size_t)k * 32 + lane];
                float f  = ((mw >> j) & 1u) ? fmaf(cl, eam[k], cg) : cg;
                bufT[(size_t)k * 32 + lane] = eg * f;
            }
        }
    }

    // ---- phase 3: ctx = W @ V ----
    {
        const int d0    = (warp & 7) * 8;
        const int kbase = (warp >> 3) * 64;
        unsigned long long cacc2[4] = {0ull, 0ull, 0ull, 0ull};

        float4 vbuf[4];
        #pragma unroll
        for (int i = 0; i < 4; i++) {          // prefetch chunk 0
            int f = tid + i * 512;
            vbuf[i] = *(const float4*)&Vp[(size_t)(f >> 4) * DD + ((f & 15) << 2)];
        }
        for (int c = 0; c < 8; c++) {
            __syncthreads();                   // pass-B (c==0) / prev compute done
            #pragma unroll
            for (int i = 0; i < 4; i++) {
                int f = tid + i * 512;
                *(float4*)&ks[(f >> 4) * 64 + ((f & 15) << 2)] = vbuf[i];
            }
            __syncthreads();
            if (c < 7) {
                #pragma unroll
                for (int i = 0; i < 4; i++) {
                    int f = tid + i * 512;
                    vbuf[i] = *(const float4*)&Vp[(size_t)((c + 1) * 128 + (f >> 4)) * DD
                                                  + ((f & 15) << 2)];
                }
            }

            #pragma unroll 4
            for (int kk = 0; kk < 64; kk++) {
                int k = kbase + kk;
                float wv = bufT[(size_t)(c * 128 + k) * 32 + lane];
                unsigned long long wp = pack2(wv, wv);
                ulonglong2 v0 = *(const ulonglong2*)&ks[k * 64 + d0];
                ulonglong2 v1 = *(const ulonglong2*)&ks[k * 64 + d0 + 4];
                ffma2(cacc2[0], wp, v0.x);
                ffma2(cacc2[1], wp, v0.y);
                ffma2(cacc2[2], wp, v1.x);
                ffma2(cacc2[3], wp, v1.y);
            }
        }

        float cacc[8];
        #pragma unroll
        for (int p = 0; p < 4; p++) {
            float2 v = unpack2(cacc2[p]);
            cacc[2 * p + 0] = v.x;
            cacc[2 * p + 1] = v.y;
        }

        if (warp >= 8) {
            #pragma unroll
            for (int j = 0; j < 8; j++)
                qs2[(warp - 8) * 256 + j * 32 + lane] = cacc[j];
        }
        __syncthreads();
        if (warp < 8) {
            #pragma unroll
            for (int j = 0; j < 8; j++)
                cacc[j] += qs2[warp * 256 + j * 32 + lane];

            int s = qbase + lane;
            size_t o = ((size_t)b * SS + s) * HIDN + h * DD + d0;
            float4 o0 = {cacc[0], cacc[1], cacc[2], cacc[3]};
            float4 o1 = {cacc[4], cacc[5], cacc[6], cacc[7]};
            *(float4*)&out[o]     = o0;
            *(float4*)&out[o + 4] = o1;
        }
    }
}

// ---------------------------------------------------------------------------
// Launch: three kernels on the capture stream. No sync, no allocation.
// ---------------------------------------------------------------------------
extern "C" void kernel_launch(void* const* d_in, const int* in_sizes, int n_in,
                              void* d_out, int out_size)
{
    const float* hs   = (const float*)d_in[0];
    const float* am   = (const float*)d_in[1];
    const int*   lmsk = (const int*)  d_in[2];
    const float* gate = (const float*)d_in[3];
    const float* Wq   = (const float*)d_in[4];
    const float* bq   = (const float*)d_in[5];
    const float* Wk   = (const float*)d_in[6];
    const float* bk   = (const float*)d_in[7];
    const float* Wv   = (const float*)d_in[8];
    const float* bv   = (const float*)d_in[9];
    float* out = (float*)d_out;

    cudaFuncSetAttribute(attn_kernel,
                         cudaFuncAttributeMaxDynamicSharedMemorySize,
                         ATTN_SMEM_BYTES);

    dim3 gm(12, 32, 3);                 // heads x m-tiles x {Q,K,V}
    qkv_mma<<<gm, 256>>>(hs, Wq, bq, Wk, bk, Wv, bv);

    dim3 gf(12, 32, 3);                 // heads x m-tiles x {Q,K,V}
    qkv_fix<<<gf, 256>>>(hs, Wq, bq, Wk, bk, Wv, bv);

    dim3 ga(32, 12, 4);                 // q-tiles x heads x batch
    attn_kernel<<<ga, 512, ATTN_SMEM_BYTES>>>(am, lmsk, gate, out);
}

// round 15
// speedup vs baseline: 1.7932x; 1.3822x over previous
#include <cuda_runtime.h>
#include <cstdint>

#define BB   4
#define SS   1024
#define HIDN 768
#define HH   12
#define DD   64

// Scratch (no cudaMalloc allowed): Q/K/V in [B,H,S,D] layout, fp32.
__device__ float g_Q[BB*HH*SS*DD];
__device__ float g_K[BB*HH*SS*DD];
__device__ float g_V[BB*HH*SS*DD];

// ---- packed fp32x2 helpers (FFMA2; used by qkv_fix fallback) ---------------
__device__ __forceinline__ void ffma2(unsigned long long& d,
                                      unsigned long long a,
                                      unsigned long long b) {
    asm("fma.rn.f32x2 %0, %1, %2, %0;" : "+l"(d) : "l"(a), "l"(b));
}
__device__ __forceinline__ unsigned long long pack2(float x, float y) {
    unsigned long long r;
    asm("mov.b64 %0, {%1, %2};" : "=l"(r) : "f"(x), "f"(y));
    return r;
}
__device__ __forceinline__ float2 unpack2(unsigned long long v) {
    float2 r;
    asm("mov.b64 {%0, %1}, %2;" : "=f"(r.x), "=f"(r.y) : "l"(v));
    return r;
}

// ---- mma.sync tf32 helpers (validated on-hardware in R14) ------------------
__device__ __forceinline__ float to_tf32(float x) {
    uint32_t r;
    asm("cvt.rna.tf32.f32 %0, %1;" : "=r"(r) : "f"(x));
    return __uint_as_float(r);
}
__device__ __forceinline__ void mma_tf32(float* d, const uint32_t* a,
                                         const uint32_t* b) {
    asm volatile(
        "mma.sync.aligned.m16n8k8.row.col.f32.tf32.tf32.f32 "
        "{%0,%1,%2,%3}, {%4,%5,%6,%7}, {%8,%9}, {%0,%1,%2,%3};"
        : "+f"(d[0]), "+f"(d[1]), "+f"(d[2]), "+f"(d[3])
        : "r"(a[0]), "r"(a[1]), "r"(a[2]), "r"(a[3]), "r"(b[0]), "r"(b[1]));
}

// ---------------------------------------------------------------------------
// Kernel 1a: QKV projection via mma.sync tf32 (unchanged from R14: 171us,
// tensor=29.8%, verified clean by qkv_fix).
// ---------------------------------------------------------------------------
__global__ __launch_bounds__(256) void qkv_mma(
    const float* __restrict__ X,
    const float* __restrict__ Wq, const float* __restrict__ bq,
    const float* __restrict__ Wk, const float* __restrict__ bk,
    const float* __restrict__ Wv, const float* __restrict__ bv)
{
    __shared__ float As[128][36];
    __shared__ float Bs[32][68];

    const float* W; const float* bias; float* out;
    if      (blockIdx.z == 0) { W = Wq; bias = bq; out = g_Q; }
    else if (blockIdx.z == 1) { W = Wk; bias = bk; out = g_K; }
    else                      { W = Wv; bias = bv; out = g_V; }

    const int tid     = threadIdx.x;
    const int wid     = tid >> 5;
    const int lane    = tid & 31;
    const int g       = lane >> 2;
    const int tig     = lane & 3;
    const int wm      = (wid & 3) * 32;
    const int wn      = (wid >> 2) * 32;
    const int head    = blockIdx.x;
    const int mbase   = blockIdx.y * 128;
    const int colBase = head * 64;

    float acc[2][4][4];
    #pragma unroll
    for (int mt = 0; mt < 2; mt++)
        #pragma unroll
        for (int nt = 0; nt < 4; nt++)
            #pragma unroll
            for (int r = 0; r < 4; r++) acc[mt][nt][r] = 0.f;

    for (int c = 0; c < 24; c++) {
        __syncthreads();
        #pragma unroll
        for (int i = 0; i < 4; i++) {
            int f  = tid + i * 256;
            int m  = f >> 3;
            int k4 = (f & 7) * 4;
            float4 v = *(const float4*)&X[(size_t)(mbase + m) * HIDN + c * 32 + k4];
            v.x = to_tf32(v.x); v.y = to_tf32(v.y);
            v.z = to_tf32(v.z); v.w = to_tf32(v.w);
            *(float4*)&As[m][k4] = v;
        }
        #pragma unroll
        for (int i = 0; i < 2; i++) {
            int f  = tid + i * 256;
            int k  = f >> 4;
            int n4 = (f & 15) * 4;
            float4 v = *(const float4*)&W[(size_t)(c * 32 + k) * HIDN + colBase + n4];
            v.x = to_tf32(v.x); v.y = to_tf32(v.y);
            v.z = to_tf32(v.z); v.w = to_tf32(v.w);
            *(float4*)&Bs[k][n4] = v;
        }
        __syncthreads();

        #pragma unroll
        for (int ks = 0; ks < 4; ks++) {
            uint32_t a[2][4], b[4][2];
            #pragma unroll
            for (int mt = 0; mt < 2; mt++) {
                int r0 = wm + mt * 16 + g;
                a[mt][0] = __float_as_uint(As[r0    ][ks * 8 + tig]);
                a[mt][1] = __float_as_uint(As[r0 + 8][ks * 8 + tig]);
                a[mt][2] = __float_as_uint(As[r0    ][ks * 8 + tig + 4]);
                a[mt][3] = __float_as_uint(As[r0 + 8][ks * 8 + tig + 4]);
            }
            #pragma unroll
            for (int nt = 0; nt < 4; nt++) {
                int n = wn + nt * 8 + g;
                b[nt][0] = __float_as_uint(Bs[ks * 8 + tig    ][n]);
                b[nt][1] = __float_as_uint(Bs[ks * 8 + tig + 4][n]);
            }
            #pragma unroll
            for (int mt = 0; mt < 2; mt++)
                #pragma unroll
                for (int nt = 0; nt < 4; nt++)
                    mma_tf32(acc[mt][nt], a[mt], b[nt]);
        }
    }

    #pragma unroll
    for (int mt = 0; mt < 2; mt++)
        #pragma unroll
        for (int rr = 0; rr < 2; rr++) {
            int m  = mbase + wm + mt * 16 + g + rr * 8;
            int bb = m >> 10, sr = m & 1023;
            #pragma unroll
            for (int nt = 0; nt < 4; nt++) {
                int d = wn + nt * 8 + 2 * tig;
                float2 o;
                o.x = acc[mt][nt][rr * 2 + 0] + bias[colBase + d];
                o.y = acc[mt][nt][rr * 2 + 1] + bias[colBase + d + 1];
                *(float2*)&out[(((size_t)bb * HH + head) * SS + sr) * DD + d] = o;
            }
        }
}

// ---------------------------------------------------------------------------
// Kernel 1b: verify-and-fix (unchanged from R14).
// ---------------------------------------------------------------------------
__global__ __launch_bounds__(256) void qkv_fix(
    const float* __restrict__ X,
    const float* __restrict__ Wq, const float* __restrict__ bq,
    const float* __restrict__ Wk, const float* __restrict__ bk,
    const float* __restrict__ Wv, const float* __restrict__ bv)
{
    __shared__ float As[16][132];
    __shared__ float Bs[16][64];
    __shared__ float red[24];
    __shared__ int   bad;

    const float* W; const float* bias; float* out;
    if      (blockIdx.z == 0) { W = Wq; bias = bq; out = g_Q; }
    else if (blockIdx.z == 1) { W = Wk; bias = bk; out = g_K; }
    else                      { W = Wv; bias = bv; out = g_V; }

    const int tid     = threadIdx.x;
    const int lane    = tid & 31;
    const int wid     = tid >> 5;
    const int rowBase = blockIdx.y * 128;
    const int head    = blockIdx.x;
    const int colBase = head * 64;

    const int mo[3] = {5, 67, 121};
    const int no[3] = {1, 29, 62};
    #pragma unroll
    for (int s = 0; s < 3; s++) {
        int gm = rowBase + mo[s];
        int n  = colBase + no[s];
        float p = 0.f;
        for (int kk = tid; kk < HIDN; kk += 256)
            p += X[(size_t)gm * HIDN + kk] * W[(size_t)kk * HIDN + n];
        #pragma unroll
        for (int o = 16; o; o >>= 1) p += __shfl_xor_sync(0xffffffffu, p, o);
        if (lane == 0) red[s * 8 + wid] = p;
    }
    if (tid == 0) bad = 0;
    __syncthreads();
    if (tid == 0) {
        int isbad = 0;
        #pragma unroll
        for (int s = 0; s < 3; s++) {
            float ref = bias[colBase + no[s]];
            #pragma unroll
            for (int w = 0; w < 8; w++) ref += red[s * 8 + w];
            int gm = rowBase + mo[s];
            int bb = gm >> 10, sr = gm & 1023;
            float got = out[(((size_t)bb * HH + head) * SS + sr) * DD + no[s]];
            if (!(fabsf(got - ref) < 0.05f)) isbad = 1;
        }
        bad = isbad;
    }
    __syncthreads();
    if (!bad) return;

    const int m0 = (tid >> 4) * 8;
    const int n0 = (tid & 15) * 4;

    unsigned long long acc2[4][4];
    #pragma unroll
    for (int j = 0; j < 4; j++)
        #pragma unroll
        for (int p = 0; p < 4; p++) acc2[j][p] = 0ull;

    for (int kt = 0; kt < 48; kt++) {
        #pragma unroll
        for (int i = 0; i < 2; i++) {
            int f  = tid + i * 256;
            int r  = f >> 2;
            int kk = (f & 3) * 4;
            float4 v = *(const float4*)&X[(size_t)(rowBase + r) * HIDN + kt * 16 + kk];
            As[kk + 0][r] = v.x; As[kk + 1][r] = v.y;
            As[kk + 2][r] = v.z; As[kk + 3][r] = v.w;
        }
        {
            int k  = tid >> 4;
            int nn = (tid & 15) * 4;
            float4 v = *(const float4*)&W[(size_t)(kt * 16 + k) * HIDN + colBase + nn];
            *(float4*)&Bs[k][nn] = v;
        }
        __syncthreads();

        #pragma unroll
        for (int k = 0; k < 16; k++) {
            ulonglong2 a01 = *(const ulonglong2*)&As[k][m0];
            ulonglong2 a23 = *(const ulonglong2*)&As[k][m0 + 4];
            float4 bb = *(const float4*)&Bs[k][n0];
            unsigned long long bp[4];
            bp[0] = pack2(bb.x, bb.x); bp[1] = pack2(bb.y, bb.y);
            bp[2] = pack2(bb.z, bb.z); bp[3] = pack2(bb.w, bb.w);
            #pragma unroll
            for (int j = 0; j < 4; j++) {
                ffma2(acc2[j][0], a01.x, bp[j]);
                ffma2(acc2[j][1], a01.y, bp[j]);
                ffma2(acc2[j][2], a23.x, bp[j]);
                ffma2(acc2[j][3], a23.y, bp[j]);
            }
        }
        __syncthreads();
    }

    float accf[8][4];
    #pragma unroll
    for (int j = 0; j < 4; j++)
        #pragma unroll
        for (int p = 0; p < 4; p++) {
            float2 v = unpack2(acc2[j][p]);
            accf[2 * p + 0][j] = v.x;
            accf[2 * p + 1][j] = v.y;
        }

    float bl[4];
    #pragma unroll
    for (int j = 0; j < 4; j++) bl[j] = bias[colBase + n0 + j];

    #pragma unroll
    for (int i = 0; i < 8; i++) {
        int r = rowBase + m0 + i;
        int b = r >> 10;
        int s = r & 1023;
        float4 o;
        o.x = accf[i][0] + bl[0]; o.y = accf[i][1] + bl[1];
        o.z = accf[i][2] + bl[2]; o.w = accf[i][3] + bl[3];
        *(float4*)&out[(((size_t)b * HH + head) * SS + s) * DD + n0] = o;
    }
}

// ---------------------------------------------------------------------------
// Kernel 2: attention via mma.sync tf32 (R15 rewrite).
// CTA = (32-q tile, h, b), 512 threads / 16 warps.
// buf[32][1028] q-major (stride 1028 ≡ 4 mod 32).
// Phase 1 (QK^T): warps 2(q)x8(k-cols). Q = A-fragments in regs. K staged
//   transposed kvT[d][136] with XOR col swizzle (key^(d&31)): staging STS and
//   B-fragment LDS both conflict-free. Scores*0.125 -> buf (float2 stores).
// Phase 2: warp owns 2 q rows; float4 sweep, eg in regs (1R+1W per elem),
//   per-warp shfl Z-reduce, gate folded: w = eg*(cg + mask*cl*eam).
// Phase 3 (PV, transposed): D^T = V^T @ P^T. V staged transposed vsT[d][132]
//   (A-loads conflict-free, bank=4g+tig); P^T = B-fragments from q-major buf
//   (conflict-free, bank=4g+tig via stride 1028). Direct STG epilogue.
// ---------------------------------------------------------------------------
#define AT_BUF   0
#define AT_KV    32896              // buf = 32*1028
#define AT_QS    41600              // kvT max(64*136, 64*132) = 8704
#define AT_AMS   43712              // qs2 = 32*66 = 2112
#define AT_EAM   44736
#define AT_GS    45760
#define AT_MB    45792
#define ATTN_SMEM_BYTES ((45792 + 1024) * 4)   // 187,264 B

__global__ __launch_bounds__(512) void attn_mma(
    const float* __restrict__ am,     // [B,1,1,S]
    const int*   __restrict__ lm,     // [B,1,S,S]
    const float* __restrict__ gate,   // [B,H,S,1]
    float* __restrict__ out)          // [B,S,HID]
{
    extern __shared__ float smf[];
    float*    buf = smf + AT_BUF;
    float*    kvT = smf + AT_KV;
    float*    qs2 = smf + AT_QS;
    float*    ams = smf + AT_AMS;
    float*    eam = smf + AT_EAM;
    float*    gs  = smf + AT_GS;
    unsigned* mb  = (unsigned*)(smf + AT_MB);   // [32 q][32 kw]

    const int tid   = threadIdx.x;
    const int lane  = tid & 31;
    const int warp  = tid >> 5;          // 0..15
    const int g     = lane >> 2;         // 0..7
    const int tig   = lane & 3;          // 0..3
    const int qtile = blockIdx.x;
    const int h     = blockIdx.y;
    const int b     = blockIdx.z;
    const int qbase = qtile * 32;
    const size_t bh = (size_t)b * HH + h;
    const float* Qp = g_Q + bh * SS * DD;
    const float* Kp = g_K + bh * SS * DD;
    const float* Vp = g_V + bh * SS * DD;

    // ---- one-time staging ----
    #pragma unroll
    for (int i = 0; i < 4; i++) {
        int idx = tid + i * 512;              // 0..2047
        int q = idx >> 6, d = idx & 63;
        qs2[q * 66 + d] = Qp[(size_t)(qbase + q) * DD + d];
    }
    if (tid < 256) {
        float4 v = *(const float4*)&am[(size_t)b * SS + tid * 4];
        *(float4*)&ams[tid * 4] = v;
    }
    if (tid < 32) gs[tid] = gate[bh * SS + qbase + tid];

    // local mask -> 1 bit, q-major mb[q][kw]
    #pragma unroll
    for (int i = 0; i < 2; i++) {
        int q = warp * 2 + i;
        const int* mrow = lm + ((size_t)b * SS + (qbase + q)) * SS;
        for (int kw = 0; kw < 32; kw++) {
            int v = mrow[kw * 32 + lane];
            unsigned bal = __ballot_sync(0xffffffffu, v != 0);
            if (lane == 0) mb[q * 32 + kw] = bal;
        }
    }
    __syncthreads();                          // qs2/ams ready
    #pragma unroll
    for (int i = 0; i < 2; i++) {
        int k = tid + i * 512;
        eam[k] = __expf(-ams[k]);
    }

    // ---- Q -> A fragments in registers (tf32-rounded) ----
    const int wmq = (warp >> 3) * 16;         // q group 0-15 / 16-31
    uint32_t aQ[8][4];
    #pragma unroll
    for (int ks = 0; ks < 8; ks++) {
        aQ[ks][0] = __float_as_uint(to_tf32(qs2[(wmq + g    ) * 66 + ks * 8 + tig    ]));
        aQ[ks][1] = __float_as_uint(to_tf32(qs2[(wmq + g + 8) * 66 + ks * 8 + tig    ]));
        aQ[ks][2] = __float_as_uint(to_tf32(qs2[(wmq + g    ) * 66 + ks * 8 + tig + 4]));
        aQ[ks][3] = __float_as_uint(to_tf32(qs2[(wmq + g + 8) * 66 + ks * 8 + tig + 4]));
    }

    // ---- phase 1: scores = (Q K^T)/8 via mma ----
    const int wnk = (warp & 7) * 16;          // key-col group within chunk
    for (int c = 0; c < 8; c++) {
        __syncthreads();
        // stage K^T: kvT[d][136], col = key ^ (d&31). Coalesced LDG; STS cf.
        #pragma unroll
        for (int i = 0; i < 4; i++) {
            int f   = tid + i * 512;
            int dg  = f & 15, key = f >> 4;
            float4 v = *(const float4*)&Kp[(size_t)(c * 128 + key) * DD + dg * 4];
            float vv[4] = {to_tf32(v.x), to_tf32(v.y), to_tf32(v.z), to_tf32(v.w)};
            #pragma unroll
            for (int j = 0; j < 4; j++) {
                int d = dg * 4 + j;
                kvT[d * 136 + (key ^ (d & 31))] = vv[j];
            }
        }
        __syncthreads();

        float accp[2][4];
        #pragma unroll
        for (int nt = 0; nt < 2; nt++)
            #pragma unroll
            for (int r = 0; r < 4; r++) accp[nt][r] = 0.f;

        #pragma unroll
        for (int ks = 0; ks < 8; ks++) {
            int d0 = ks * 8 + tig, d1 = d0 + 4;
            uint32_t bf[2][2];
            #pragma unroll
            for (int nt = 0; nt < 2; nt++) {
                int key = wnk + nt * 8 + g;
                bf[nt][0] = __float_as_uint(kvT[d0 * 136 + (key ^ (d0 & 31))]);
                bf[nt][1] = __float_as_uint(kvT[d1 * 136 + (key ^ (d1 & 31))]);
            }
            mma_tf32(accp[0], aQ[ks], bf[0]);
            mma_tf32(accp[1], aQ[ks], bf[1]);
        }
        #pragma unroll
        for (int nt = 0; nt < 2; nt++) {
            int kc = c * 128 + wnk + nt * 8 + 2 * tig;
            float2 lo = {accp[nt][0] * 0.125f, accp[nt][1] * 0.125f};
            float2 hi = {accp[nt][2] * 0.125f, accp[nt][3] * 0.125f};
            *(float2*)&buf[(wmq + g    ) * 1028 + kc] = lo;
            *(float2*)&buf[(wmq + g + 8) * 1028 + kc] = hi;
        }
    }
    __syncthreads();

    // ---- phase 2: dual softmax + gate fold (warp owns rows 2w, 2w+1) ----
    #pragma unroll
    for (int i = 0; i < 2; i++) {
        int q = warp * 2 + i;
        float* row = buf + q * 1028;
        const unsigned* mbq = mb + q * 32;
        const int bb2 = (lane & 7) * 4;

        float4 eg[8];
        float zg = 0.f, zl = 0.f;
        #pragma unroll
        for (int kb = 0; kb < 8; kb++) {
            int k = kb * 128 + lane * 4;
            float4 s4 = *(const float4*)&row[k];
            float4 a4 = *(const float4*)&ams[k];
            float4 e4 = *(const float4*)&eam[k];
            unsigned mw = mbq[kb * 4 + (lane >> 3)];
            float4 e;
            e.x = __expf(s4.x + a4.x); e.y = __expf(s4.y + a4.y);
            e.z = __expf(s4.z + a4.z); e.w = __expf(s4.w + a4.w);
            eg[kb] = e;
            zg += (e.x + e.y) + (e.z + e.w);
            zl += (((mw >> (bb2 + 0)) & 1u) ? e.x * e4.x : 0.f)
                + (((mw >> (bb2 + 1)) & 1u) ? e.y * e4.y : 0.f)
                + (((mw >> (bb2 + 2)) & 1u) ? e.z * e4.z : 0.f)
                + (((mw >> (bb2 + 3)) & 1u) ? e.w * e4.w : 0.f);
        }
        #pragma unroll
        for (int o = 16; o; o >>= 1) {
            zg += __shfl_xor_sync(0xffffffffu, zg, o);
            zl += __shfl_xor_sync(0xffffffffu, zl, o);
        }
        float gg = gs[q];
        float cg = (1.f - gg) / zg;
        float cl = gg / zl;
        #pragma unroll
        for (int kb = 0; kb < 8; kb++) {
            int k = kb * 128 + lane * 4;
            float4 e4 = *(const float4*)&eam[k];
            unsigned mw = mbq[kb * 4 + (lane >> 3)];
            float4 w;
            w.x = eg[kb].x * (((mw >> (bb2 + 0)) & 1u) ? fmaf(cl, e4.x, cg) : cg);
            w.y = eg[kb].y * (((mw >> (bb2 + 1)) & 1u) ? fmaf(cl, e4.y, cg) : cg);
            w.z = eg[kb].z * (((mw >> (bb2 + 2)) & 1u) ? fmaf(cl, e4.z, cg) : cg);
            w.w = eg[kb].w * (((mw >> (bb2 + 3)) & 1u) ? fmaf(cl, e4.w, cg) : cg);
            *(float4*)&row[k] = w;
        }
    }
    __syncthreads();

    // ---- phase 3: ctx^T = V^T @ P^T via mma ----
    const int wmd = (warp >> 2) * 16;         // d group (4 of them)
    const int qt  = (warp & 3) * 8;           // q col group (4 of them)
    float acc[4] = {0.f, 0.f, 0.f, 0.f};

    for (int c = 0; c < 8; c++) {
        // stage V^T: vsT[d][132] plain (A-loads cf; staging 4-way accepted)
        #pragma unroll
        for (int i = 0; i < 4; i++) {
            int f   = tid + i * 512;
            int dg  = f & 15, key = f >> 4;
            float4 v = *(const float4*)&Vp[(size_t)(c * 128 + key) * DD + dg * 4];
            kvT[(dg * 4 + 0) * 132 + key] = to_tf32(v.x);
            kvT[(dg * 4 + 1) * 132 + key] = to_tf32(v.y);
            kvT[(dg * 4 + 2) * 132 + key] = to_tf32(v.z);
            kvT[(dg * 4 + 3) * 132 + key] = to_tf32(v.w);
        }
        __syncthreads();

        #pragma unroll 4
        for (int ks = 0; ks < 16; ks++) {
            int kk = ks * 8 + tig;
            uint32_t a[4], bb[2];
            a[0] = __float_as_uint(kvT[(wmd + g    ) * 132 + kk    ]);
            a[1] = __float_as_uint(kvT[(wmd + g + 8) * 132 + kk    ]);
            a[2] = __float_as_uint(kvT[(wmd + g    ) * 132 + kk + 4]);
            a[3] = __float_as_uint(kvT[(wmd + g + 8) * 132 + kk + 4]);
            bb[0] = __float_as_uint(to_tf32(buf[(qt + g) * 1028 + c * 128 + kk    ]));
            bb[1] = __float_as_uint(to_tf32(buf[(qt + g) * 1028 + c * 128 + kk + 4]));
            mma_tf32(acc, a, bb);
        }
        __syncthreads();                      // before restaging kvT
    }

    // ---- epilogue: D^T fragments -> gmem (c0:(d,q0) c1:(d,q0+1) c2/c3: d+8)
    {
        int d  = wmd + g;
        int q0 = qt + 2 * tig;
        size_t r0 = ((size_t)b * SS + qbase + q0    ) * HIDN + h * DD;
        size_t r1 = ((size_t)b * SS + qbase + q0 + 1) * HIDN + h * DD;
        out[r0 + d]     = acc[0];
        out[r1 + d]     = acc[1];
        out[r0 + d + 8] = acc[2];
        out[r1 + d + 8] = acc[3];
    }
}

// ---------------------------------------------------------------------------
// Launch: three kernels on the capture stream. No sync, no allocation.
// ---------------------------------------------------------------------------
extern "C" void kernel_launch(void* const* d_in, const int* in_sizes, int n_in,
                              void* d_out, int out_size)
{
    const float* hs   = (const float*)d_in[0];
    const float* am   = (const float*)d_in[1];
    const int*   lmsk = (const int*)  d_in[2];
    const float* gate = (const float*)d_in[3];
    const float* Wq   = (const float*)d_in[4];
    const float* bq   = (const float*)d_in[5];
    const float* Wk   = (const float*)d_in[6];
    const float* bk   = (const float*)d_in[7];
    const float* Wv   = (const float*)d_in[8];
    const float* bv   = (const float*)d_in[9];
    float* out = (float*)d_out;

    cudaFuncSetAttribute(attn_mma,
                         cudaFuncAttributeMaxDynamicSharedMemorySize,
                         ATTN_SMEM_BYTES);

    dim3 gm(12, 32, 3);                 // heads x m-tiles x {Q,K,V}
    qkv_mma<<<gm, 256>>>(hs, Wq, bq, Wk, bk, Wv, bv);

    dim3 gf(12, 32, 3);
    qkv_fix<<<gf, 256>>>(hs, Wq, bq, Wk, bk, Wv, bv);

    dim3 ga(32, 12, 4);                 // q-tiles x heads x batch
    attn_mma<<<ga, 512, ATTN_SMEM_BYTES>>>(am, lmsk, gate, out);
}

// round 16
// speedup vs baseline: 2.1650x; 1.2073x over previous
#include <cuda_runtime.h>
#include <cstdint>

#define BB   4
#define SS   1024
#define HIDN 768
#define HH   12
#define DD   64

// Scratch (no cudaMalloc allowed): Q/K/V in [B,H,S,D] layout, fp32.
__device__ float g_Q[BB*HH*SS*DD];
__device__ float g_K[BB*HH*SS*DD];
__device__ float g_V[BB*HH*SS*DD];

// ---- packed fp32x2 helpers (FFMA2; used by qkv_fix fallback) ---------------
__device__ __forceinline__ void ffma2(unsigned long long& d,
                                      unsigned long long a,
                                      unsigned long long b) {
    asm("fma.rn.f32x2 %0, %1, %2, %0;" : "+l"(d) : "l"(a), "l"(b));
}
__device__ __forceinline__ unsigned long long pack2(float x, float y) {
    unsigned long long r;
    asm("mov.b64 %0, {%1, %2};" : "=l"(r) : "f"(x), "f"(y));
    return r;
}
__device__ __forceinline__ float2 unpack2(unsigned long long v) {
    float2 r;
    asm("mov.b64 {%0, %1}, %2;" : "=f"(r.x), "=f"(r.y) : "l"(v));
    return r;
}

// ---- mma.sync tf32 helpers (hardware-validated R14/R15) --------------------
__device__ __forceinline__ float to_tf32(float x) {
    uint32_t r;
    asm("cvt.rna.tf32.f32 %0, %1;" : "=r"(r) : "f"(x));
    return __uint_as_float(r);
}
__device__ __forceinline__ void mma_tf32(float* d, const uint32_t* a,
                                         const uint32_t* b) {
    asm volatile(
        "mma.sync.aligned.m16n8k8.row.col.f32.tf32.tf32.f32 "
        "{%0,%1,%2,%3}, {%4,%5,%6,%7}, {%8,%9}, {%0,%1,%2,%3};"
        : "+f"(d[0]), "+f"(d[1]), "+f"(d[2]), "+f"(d[3])
        : "r"(a[0]), "r"(a[1]), "r"(a[2]), "r"(a[3]), "r"(b[0]), "r"(b[1]));
}

// ---------------------------------------------------------------------------
// Kernel 1a: QKV projection via mma.sync tf32 (unchanged; 173us measured).
// ---------------------------------------------------------------------------
__global__ __launch_bounds__(256) void qkv_mma(
    const float* __restrict__ X,
    const float* __restrict__ Wq, const float* __restrict__ bq,
    const float* __restrict__ Wk, const float* __restrict__ bk,
    const float* __restrict__ Wv, const float* __restrict__ bv)
{
    __shared__ float As[128][36];
    __shared__ float Bs[32][68];

    const float* W; const float* bias; float* out;
    if      (blockIdx.z == 0) { W = Wq; bias = bq; out = g_Q; }
    else if (blockIdx.z == 1) { W = Wk; bias = bk; out = g_K; }
    else                      { W = Wv; bias = bv; out = g_V; }

    const int tid     = threadIdx.x;
    const int wid     = tid >> 5;
    const int lane    = tid & 31;
    const int g       = lane >> 2;
    const int tig     = lane & 3;
    const int wm      = (wid & 3) * 32;
    const int wn      = (wid >> 2) * 32;
    const int head    = blockIdx.x;
    const int mbase   = blockIdx.y * 128;
    const int colBase = head * 64;

    float acc[2][4][4];
    #pragma unroll
    for (int mt = 0; mt < 2; mt++)
        #pragma unroll
        for (int nt = 0; nt < 4; nt++)
            #pragma unroll
            for (int r = 0; r < 4; r++) acc[mt][nt][r] = 0.f;

    for (int c = 0; c < 24; c++) {
        __syncthreads();
        #pragma unroll
        for (int i = 0; i < 4; i++) {
            int f  = tid + i * 256;
            int m  = f >> 3;
            int k4 = (f & 7) * 4;
            float4 v = *(const float4*)&X[(size_t)(mbase + m) * HIDN + c * 32 + k4];
            v.x = to_tf32(v.x); v.y = to_tf32(v.y);
            v.z = to_tf32(v.z); v.w = to_tf32(v.w);
            *(float4*)&As[m][k4] = v;
        }
        #pragma unroll
        for (int i = 0; i < 2; i++) {
            int f  = tid + i * 256;
            int k  = f >> 4;
            int n4 = (f & 15) * 4;
            float4 v = *(const float4*)&W[(size_t)(c * 32 + k) * HIDN + colBase + n4];
            v.x = to_tf32(v.x); v.y = to_tf32(v.y);
            v.z = to_tf32(v.z); v.w = to_tf32(v.w);
            *(float4*)&Bs[k][n4] = v;
        }
        __syncthreads();

        #pragma unroll
        for (int ks = 0; ks < 4; ks++) {
            uint32_t a[2][4], b[4][2];
            #pragma unroll
            for (int mt = 0; mt < 2; mt++) {
                int r0 = wm + mt * 16 + g;
                a[mt][0] = __float_as_uint(As[r0    ][ks * 8 + tig]);
                a[mt][1] = __float_as_uint(As[r0 + 8][ks * 8 + tig]);
                a[mt][2] = __float_as_uint(As[r0    ][ks * 8 + tig + 4]);
                a[mt][3] = __float_as_uint(As[r0 + 8][ks * 8 + tig + 4]);
            }
            #pragma unroll
            for (int nt = 0; nt < 4; nt++) {
                int n = wn + nt * 8 + g;
                b[nt][0] = __float_as_uint(Bs[ks * 8 + tig    ][n]);
                b[nt][1] = __float_as_uint(Bs[ks * 8 + tig + 4][n]);
            }
            #pragma unroll
            for (int mt = 0; mt < 2; mt++)
                #pragma unroll
                for (int nt = 0; nt < 4; nt++)
                    mma_tf32(acc[mt][nt], a[mt], b[nt]);
        }
    }

    #pragma unroll
    for (int mt = 0; mt < 2; mt++)
        #pragma unroll
        for (int rr = 0; rr < 2; rr++) {
            int m  = mbase + wm + mt * 16 + g + rr * 8;
            int bb = m >> 10, sr = m & 1023;
            #pragma unroll
            for (int nt = 0; nt < 4; nt++) {
                int d = wn + nt * 8 + 2 * tig;
                float2 o;
                o.x = acc[mt][nt][rr * 2 + 0] + bias[colBase + d];
                o.y = acc[mt][nt][rr * 2 + 1] + bias[colBase + d + 1];
                *(float2*)&out[(((size_t)bb * HH + head) * SS + sr) * DD + d] = o;
            }
        }
}

// ---------------------------------------------------------------------------
// Kernel 1b: verify-and-fix (unchanged).
// ---------------------------------------------------------------------------
__global__ __launch_bounds__(256) void qkv_fix(
    const float* __restrict__ X,
    const float* __restrict__ Wq, const float* __restrict__ bq,
    const float* __restrict__ Wk, const float* __restrict__ bk,
    const float* __restrict__ Wv, const float* __restrict__ bv)
{
    __shared__ float As[16][132];
    __shared__ float Bs[16][64];
    __shared__ float red[24];
    __shared__ int   bad;

    const float* W; const float* bias; float* out;
    if      (blockIdx.z == 0) { W = Wq; bias = bq; out = g_Q; }
    else if (blockIdx.z == 1) { W = Wk; bias = bk; out = g_K; }
    else                      { W = Wv; bias = bv; out = g_V; }

    const int tid     = threadIdx.x;
    const int lane    = tid & 31;
    const int wid     = tid >> 5;
    const int rowBase = blockIdx.y * 128;
    const int head    = blockIdx.x;
    const int colBase = head * 64;

    const int mo[3] = {5, 67, 121};
    const int no[3] = {1, 29, 62};
    #pragma unroll
    for (int s = 0; s < 3; s++) {
        int gm = rowBase + mo[s];
        int n  = colBase + no[s];
        float p = 0.f;
        for (int kk = tid; kk < HIDN; kk += 256)
            p += X[(size_t)gm * HIDN + kk] * W[(size_t)kk * HIDN + n];
        #pragma unroll
        for (int o = 16; o; o >>= 1) p += __shfl_xor_sync(0xffffffffu, p, o);
        if (lane == 0) red[s * 8 + wid] = p;
    }
    if (tid == 0) bad = 0;
    __syncthreads();
    if (tid == 0) {
        int isbad = 0;
        #pragma unroll
        for (int s = 0; s < 3; s++) {
            float ref = bias[colBase + no[s]];
            #pragma unroll
            for (int w = 0; w < 8; w++) ref += red[s * 8 + w];
            int gm = rowBase + mo[s];
            int bb = gm >> 10, sr = gm & 1023;
            float got = out[(((size_t)bb * HH + head) * SS + sr) * DD + no[s]];
            if (!(fabsf(got - ref) < 0.05f)) isbad = 1;
        }
        bad = isbad;
    }
    __syncthreads();
    if (!bad) return;

    const int m0 = (tid >> 4) * 8;
    const int n0 = (tid & 15) * 4;

    unsigned long long acc2[4][4];
    #pragma unroll
    for (int j = 0; j < 4; j++)
        #pragma unroll
        for (int p = 0; p < 4; p++) acc2[j][p] = 0ull;

    for (int kt = 0; kt < 48; kt++) {
        #pragma unroll
        for (int i = 0; i < 2; i++) {
            int f  = tid + i * 256;
            int r  = f >> 2;
            int kk = (f & 3) * 4;
            float4 v = *(const float4*)&X[(size_t)(rowBase + r) * HIDN + kt * 16 + kk];
            As[kk + 0][r] = v.x; As[kk + 1][r] = v.y;
            As[kk + 2][r] = v.z; As[kk + 3][r] = v.w;
        }
        {
            int k  = tid >> 4;
            int nn = (tid & 15) * 4;
            float4 v = *(const float4*)&W[(size_t)(kt * 16 + k) * HIDN + colBase + nn];
            *(float4*)&Bs[k][nn] = v;
        }
        __syncthreads();

        #pragma unroll
        for (int k = 0; k < 16; k++) {
            ulonglong2 a01 = *(const ulonglong2*)&As[k][m0];
            ulonglong2 a23 = *(const ulonglong2*)&As[k][m0 + 4];
            float4 bb = *(const float4*)&Bs[k][n0];
            unsigned long long bp[4];
            bp[0] = pack2(bb.x, bb.x); bp[1] = pack2(bb.y, bb.y);
            bp[2] = pack2(bb.z, bb.z); bp[3] = pack2(bb.w, bb.w);
            #pragma unroll
            for (int j = 0; j < 4; j++) {
                ffma2(acc2[j][0], a01.x, bp[j]);
                ffma2(acc2[j][1], a01.y, bp[j]);
                ffma2(acc2[j][2], a23.x, bp[j]);
                ffma2(acc2[j][3], a23.y, bp[j]);
            }
        }
        __syncthreads();
    }

    float accf[8][4];
    #pragma unroll
    for (int j = 0; j < 4; j++)
        #pragma unroll
        for (int p = 0; p < 4; p++) {
            float2 v = unpack2(acc2[j][p]);
            accf[2 * p + 0][j] = v.x;
            accf[2 * p + 1][j] = v.y;
        }

    float bl[4];
    #pragma unroll
    for (int j = 0; j < 4; j++) bl[j] = bias[colBase + n0 + j];

    #pragma unroll
    for (int i = 0; i < 8; i++) {
        int r = rowBase + m0 + i;
        int b = r >> 10;
        int s = r & 1023;
        float4 o;
        o.x = accf[i][0] + bl[0]; o.y = accf[i][1] + bl[1];
        o.z = accf[i][2] + bl[2]; o.w = accf[i][3] + bl[3];
        *(float4*)&out[(((size_t)b * HH + head) * SS + s) * DD + n0] = o;
    }
}

// ---------------------------------------------------------------------------
// Kernel 2: attention via mma.sync tf32 (R16).
// CTA = (32-q tile, h, b), 512 threads / 16 warps, smem 222,080 B.
// kv[2][128][68]: natural key-major, float4 staging, DOUBLE-BUFFERED with
//   LDG-before-compute prefetch; 1 sync/chunk.
//   Phase-1 B-loads: bank = 4g+tig+8ks (cf). Phase-3 V B-loads: 4tig+g (cf).
// buf[32][1028] q-major scores -> tf32 weights (pre-rounded in phase 2).
// Phase 3: D = P @ V; warps 2(q16) x 8(d8); P A-frags from buf (cf),
//   float2 epilogue.
// ---------------------------------------------------------------------------
#define AT_BUF   0
#define AT_KV0   32896
#define AT_KV1   (32896 + 8704)
#define AT_QS    50304
#define AT_AMS   52416
#define AT_EAM   53440
#define AT_GS    54464
#define AT_MB    54496
#define ATTN_SMEM_BYTES ((54496 + 1024) * 4)   // 222,080 B

__global__ __launch_bounds__(512, 1) void attn_mma(
    const float* __restrict__ am,     // [B,1,1,S]
    const int*   __restrict__ lm,     // [B,1,S,S]
    const float* __restrict__ gate,   // [B,H,S,1]
    float* __restrict__ out)          // [B,S,HID]
{
    extern __shared__ float smf[];
    float*    buf = smf + AT_BUF;
    float*    qs2 = smf + AT_QS;
    float*    ams = smf + AT_AMS;
    float*    eam = smf + AT_EAM;
    float*    gs  = smf + AT_GS;
    unsigned* mb  = (unsigned*)(smf + AT_MB);   // [32 q][32 kw]

    const int tid   = threadIdx.x;
    const int lane  = tid & 31;
    const int warp  = tid >> 5;          // 0..15
    const int g     = lane >> 2;         // 0..7
    const int tig   = lane & 3;          // 0..3
    const int qtile = blockIdx.x;
    const int h     = blockIdx.y;
    const int b     = blockIdx.z;
    const int qbase = qtile * 32;
    const size_t bh = (size_t)b * HH + h;
    const float* Qp = g_Q + bh * SS * DD;
    const float* Kp = g_K + bh * SS * DD;
    const float* Vp = g_V + bh * SS * DD;

    const int skey = tid >> 4;           // staging: key row 0..31 (+32i)
    const int sdg  = (tid & 15) * 4;     // staging: d offset

    // ---- one-time staging ----
    #pragma unroll
    for (int i = 0; i < 4; i++) {
        int idx = tid + i * 512;              // 0..2047
        int q = idx >> 6, d = idx & 63;
        qs2[q * 66 + d] = Qp[(size_t)(qbase + q) * DD + d];
    }
    if (tid < 256) {
        float4 v = *(const float4*)&am[(size_t)b * SS + tid * 4];
        *(float4*)&ams[tid * 4] = v;
    }
    if (tid < 32) gs[tid] = gate[bh * SS + qbase + tid];

    #pragma unroll
    for (int i = 0; i < 2; i++) {
        int q = warp * 2 + i;
        const int* mrow = lm + ((size_t)b * SS + (qbase + q)) * SS;
        for (int kw = 0; kw < 32; kw++) {
            int v = mrow[kw * 32 + lane];
            unsigned bal = __ballot_sync(0xffffffffu, v != 0);
            if (lane == 0) mb[q * 32 + kw] = bal;
        }
    }
    __syncthreads();                          // qs2/ams ready
    #pragma unroll
    for (int i = 0; i < 2; i++) {
        int k = tid + i * 512;
        eam[k] = __expf(-ams[k]);
    }

    // ---- Q -> A fragments in registers (tf32) ----
    const int wmq = (warp >> 3) * 16;
    uint32_t aQ[8][4];
    #pragma unroll
    for (int ks = 0; ks < 8; ks++) {
        aQ[ks][0] = __float_as_uint(to_tf32(qs2[(wmq + g    ) * 66 + ks * 8 + tig    ]));
        aQ[ks][1] = __float_as_uint(to_tf32(qs2[(wmq + g + 8) * 66 + ks * 8 + tig    ]));
        aQ[ks][2] = __float_as_uint(to_tf32(qs2[(wmq + g    ) * 66 + ks * 8 + tig + 4]));
        aQ[ks][3] = __float_as_uint(to_tf32(qs2[(wmq + g + 8) * 66 + ks * 8 + tig + 4]));
    }

    // ---- phase 1: scores = (Q K^T)/8, double-buffered K ----
    const int wnk = (warp & 7) * 16;
    {
        // stage chunk 0 into kv0
        #pragma unroll
        for (int i = 0; i < 4; i++) {
            int key = skey + i * 32;
            float4 v = *(const float4*)&Kp[(size_t)key * DD + sdg];
            float* dst = smf + AT_KV0 + key * 68 + sdg;
            dst[0] = to_tf32(v.x); dst[1] = to_tf32(v.y);
            dst[2] = to_tf32(v.z); dst[3] = to_tf32(v.w);
        }
        __syncthreads();

        for (int c = 0; c < 8; c++) {
            const float* kvc = smf + ((c & 1) ? AT_KV1 : AT_KV0);
            float*       kvn = smf + ((c & 1) ? AT_KV0 : AT_KV1);

            float4 pre[4];
            if (c < 7) {
                #pragma unroll
                for (int i = 0; i < 4; i++) {
                    int key = skey + i * 32;
                    pre[i] = *(const float4*)&Kp[(size_t)((c + 1) * 128 + key) * DD + sdg];
                }
            }

            float accp[2][4];
            #pragma unroll
            for (int nt = 0; nt < 2; nt++)
                #pragma unroll
                for (int r = 0; r < 4; r++) accp[nt][r] = 0.f;

            #pragma unroll
            for (int ks = 0; ks < 8; ks++) {
                int d0 = ks * 8 + tig;
                uint32_t bf[2][2];
                #pragma unroll
                for (int nt = 0; nt < 2; nt++) {
                    int key = wnk + nt * 8 + g;
                    bf[nt][0] = __float_as_uint(kvc[key * 68 + d0    ]);
                    bf[nt][1] = __float_as_uint(kvc[key * 68 + d0 + 4]);
                }
                mma_tf32(accp[0], aQ[ks], bf[0]);
                mma_tf32(accp[1], aQ[ks], bf[1]);
            }
            #pragma unroll
            for (int nt = 0; nt < 2; nt++) {
                int kc = c * 128 + wnk + nt * 8 + 2 * tig;
                float2 lo = {accp[nt][0] * 0.125f, accp[nt][1] * 0.125f};
                float2 hi = {accp[nt][2] * 0.125f, accp[nt][3] * 0.125f};
                *(float2*)&buf[(wmq + g    ) * 1028 + kc] = lo;
                *(float2*)&buf[(wmq + g + 8) * 1028 + kc] = hi;
            }

            if (c < 7) {
                #pragma unroll
                for (int i = 0; i < 4; i++) {
                    int key = skey + i * 32;
                    float* dst = kvn + key * 68 + sdg;
                    dst[0] = to_tf32(pre[i].x); dst[1] = to_tf32(pre[i].y);
                    dst[2] = to_tf32(pre[i].z); dst[3] = to_tf32(pre[i].w);
                }
            }
            __syncthreads();
        }
    }

    // ---- phase 2: dual softmax + gate fold; weights stored tf32 ----
    #pragma unroll
    for (int i = 0; i < 2; i++) {
        int q = warp * 2 + i;
        float* row = buf + q * 1028;
        const unsigned* mbq = mb + q * 32;
        const int bb2 = (lane & 7) * 4;

        float4 eg[8];
        float zg = 0.f, zl = 0.f;
        #pragma unroll
        for (int kb = 0; kb < 8; kb++) {
            int k = kb * 128 + lane * 4;
            float4 s4 = *(const float4*)&row[k];
            float4 a4 = *(const float4*)&ams[k];
            float4 e4 = *(const float4*)&eam[k];
            unsigned mw = mbq[kb * 4 + (lane >> 3)];
            float4 e;
            e.x = __expf(s4.x + a4.x); e.y = __expf(s4.y + a4.y);
            e.z = __expf(s4.z + a4.z); e.w = __expf(s4.w + a4.w);
            eg[kb] = e;
            zg += (e.x + e.y) + (e.z + e.w);
            zl += (((mw >> (bb2 + 0)) & 1u) ? e.x * e4.x : 0.f)
                + (((mw >> (bb2 + 1)) & 1u) ? e.y * e4.y : 0.f)
                + (((mw >> (bb2 + 2)) & 1u) ? e.z * e4.z : 0.f)
                + (((mw >> (bb2 + 3)) & 1u) ? e.w * e4.w : 0.f);
        }
        #pragma unroll
        for (int o = 16; o; o >>= 1) {
            zg += __shfl_xor_sync(0xffffffffu, zg, o);
            zl += __shfl_xor_sync(0xffffffffu, zl, o);
        }
        float gg = gs[q];
        float cg = (1.f - gg) / zg;
        float cl = gg / zl;
        #pragma unroll
        for (int kb = 0; kb < 8; kb++) {
            int k = kb * 128 + lane * 4;
            float4 e4 = *(const float4*)&eam[k];
            unsigned mw = mbq[kb * 4 + (lane >> 3)];
            float4 w;
            w.x = to_tf32(eg[kb].x * (((mw >> (bb2 + 0)) & 1u) ? fmaf(cl, e4.x, cg) : cg));
            w.y = to_tf32(eg[kb].y * (((mw >> (bb2 + 1)) & 1u) ? fmaf(cl, e4.y, cg) : cg));
            w.z = to_tf32(eg[kb].z * (((mw >> (bb2 + 2)) & 1u) ? fmaf(cl, e4.z, cg) : cg));
            w.w = to_tf32(eg[kb].w * (((mw >> (bb2 + 3)) & 1u) ? fmaf(cl, e4.w, cg) : cg));
            *(float4*)&row[k] = w;
        }
    }

    // ---- phase 3: ctx = P @ V, double-buffered V ----
    const int wn3 = (warp & 7) * 8;           // d-col group
    float acc[4] = {0.f, 0.f, 0.f, 0.f};
    {
        // stage V chunk 0 into kv0 (kv free: phase 2 touched only buf)
        #pragma unroll
        for (int i = 0; i < 4; i++) {
            int key = skey + i * 32;
            float4 v = *(const float4*)&Vp[(size_t)key * DD + sdg];
            float* dst = smf + AT_KV0 + key * 68 + sdg;
            dst[0] = to_tf32(v.x); dst[1] = to_tf32(v.y);
            dst[2] = to_tf32(v.z); dst[3] = to_tf32(v.w);
        }
        __syncthreads();                      // also orders phase-2 buf writes

        for (int c = 0; c < 8; c++) {
            const float* kvc = smf + ((c & 1) ? AT_KV1 : AT_KV0);
            float*       kvn = smf + ((c & 1) ? AT_KV0 : AT_KV1);

            float4 pre[4];
            if (c < 7) {
                #pragma unroll
                for (int i = 0; i < 4; i++) {
                    int key = skey + i * 32;
                    pre[i] = *(const float4*)&Vp[(size_t)((c + 1) * 128 + key) * DD + sdg];
                }
            }

            const float* p0 = buf + (wmq + g    ) * 1028 + c * 128;
            const float* p1 = buf + (wmq + g + 8) * 1028 + c * 128;
            #pragma unroll 4
            for (int ks = 0; ks < 16; ks++) {
                int kk = ks * 8 + tig;
                uint32_t a[4], bb[2];
                a[0] = __float_as_uint(p0[kk    ]);
                a[1] = __float_as_uint(p1[kk    ]);
                a[2] = __float_as_uint(p0[kk + 4]);
                a[3] = __float_as_uint(p1[kk + 4]);
                bb[0] = __float_as_uint(kvc[(kk    ) * 68 + wn3 + g]);
                bb[1] = __float_as_uint(kvc[(kk + 4) * 68 + wn3 + g]);
                mma_tf32(acc, a, bb);
            }

            if (c < 7) {
                #pragma unroll
                for (int i = 0; i < 4; i++) {
                    int key = skey + i * 32;
                    float* dst = kvn + key * 68 + sdg;
                    dst[0] = to_tf32(pre[i].x); dst[1] = to_tf32(pre[i].y);
                    dst[2] = to_tf32(pre[i].z); dst[3] = to_tf32(pre[i].w);
                }
            }
            __syncthreads();
        }
    }

    // ---- epilogue: C rows (q=wmq+g, +8), cols (wn3+2tig, +1) ----
    {
        int q0   = qbase + wmq + g;
        int dcol = h * DD + wn3 + 2 * tig;
        float2 o0 = {acc[0], acc[1]};
        float2 o1 = {acc[2], acc[3]};
        *(float2*)&out[((size_t)b * SS + q0    ) * HIDN + dcol] = o0;
        *(float2*)&out[((size_t)b * SS + q0 + 8) * HIDN + dcol] = o1;
    }
}

// ---------------------------------------------------------------------------
// Launch: three kernels on the capture stream. No sync, no allocation.
// ---------------------------------------------------------------------------
extern "C" void kernel_launch(void* const* d_in, const int* in_sizes, int n_in,
                              void* d_out, int out_size)
{
    const float* hs   = (const float*)d_in[0];
    const float* am   = (const float*)d_in[1];
    const int*   lmsk = (const int*)  d_in[2];
    const float* gate = (const float*)d_in[3];
    const float* Wq   = (const float*)d_in[4];
    const float* bq   = (const float*)d_in[5];
    const float* Wk   = (const float*)d_in[6];
    const float* bk   = (const float*)d_in[7];
    const float* Wv   = (const float*)d_in[8];
    const float* bv   = (const float*)d_in[9];
    float* out = (float*)d_out;

    cudaFuncSetAttribute(attn_mma,
                         cudaFuncAttributeMaxDynamicSharedMemorySize,
                         ATTN_SMEM_BYTES);

    dim3 gm(12, 32, 3);                 // heads x m-tiles x {Q,K,V}
    qkv_mma<<<gm, 256>>>(hs, Wq, bq, Wk, bk, Wv, bv);

    dim3 gf(12, 32, 3);
    qkv_fix<<<gf, 256>>>(hs, Wq, bq, Wk, bk, Wv, bv);

    dim3 ga(32, 12, 4);                 // q-tiles x heads x batch
    attn_mma<<<ga, 512, ATTN_SMEM_BYTES>>>(am, lmsk, gate, out);
}

// round 17
// speedup vs baseline: 2.3147x; 1.0692x over previous
#include <cuda_runtime.h>
#include <cstdint>

#define BB   4
#define SS   1024
#define HIDN 768
#define HH   12
#define DD   64

// Scratch (no cudaMalloc allowed): Q/K/V in [B,H,S,D] layout, fp32.
__device__ float    g_Q[BB*HH*SS*DD];
__device__ float    g_K[BB*HH*SS*DD];
__device__ float    g_V[BB*HH*SS*DD];
__device__ unsigned g_mbits[BB*SS*32];   // bit-packed local mask [b][q][kw]

// ---- mma.sync tf32 helpers (hardware-validated R14-R16) --------------------
__device__ __forceinline__ float to_tf32(float x) {
    uint32_t r;
    asm("cvt.rna.tf32.f32 %0, %1;" : "=r"(r) : "f"(x));
    return __uint_as_float(r);
}
__device__ __forceinline__ void mma_tf32(float* d, const uint32_t* a,
                                         const uint32_t* b) {
    asm volatile(
        "mma.sync.aligned.m16n8k8.row.col.f32.tf32.tf32.f32 "
        "{%0,%1,%2,%3}, {%4,%5,%6,%7}, {%8,%9}, {%0,%1,%2,%3};"
        : "+f"(d[0]), "+f"(d[1]), "+f"(d[2]), "+f"(d[3])
        : "r"(a[0]), "r"(a[1]), "r"(a[2]), "r"(a[3]), "r"(b[0]), "r"(b[1]));
}

// ---------------------------------------------------------------------------
// Kernel 0: pack local mask to bits ONCE (kills the 12x-redundant 192MB of
// lm reads + per-CTA ballots in attn). One warp per (b,q) row.
// ---------------------------------------------------------------------------
__global__ __launch_bounds__(256) void pack_mask(const int* __restrict__ lm)
{
    int wid  = (blockIdx.x * 256 + threadIdx.x) >> 5;   // 0..4095 = b*1024+q
    int lane = threadIdx.x & 31;
    const int* row = lm + (size_t)wid * SS;
    unsigned*  dst = g_mbits + (size_t)wid * 32;
    #pragma unroll
    for (int kw = 0; kw < 32; kw++) {
        unsigned bal = __ballot_sync(0xffffffffu, row[kw * 32 + lane] != 0);
        if (lane == 0) dst[kw] = bal;
    }
}

// ---------------------------------------------------------------------------
// Kernel 1: QKV projection via mma.sync tf32. R17: BK=64 (12 chunks, 24
// syncs instead of 48), dynamic smem 52,224B. Banking unchanged-safe:
// row strides 68 ≡ 4 (mod 32), fragment loads stay conflict-free.
// Fragment layouts hardware-validated (R14-R16) -> qkv_fix retired.
// ---------------------------------------------------------------------------
#define QKV_SMEM_BYTES ((128*68 + 64*68) * 4)   // 52,224 B

__global__ __launch_bounds__(256) void qkv_mma(
    const float* __restrict__ X,
    const float* __restrict__ Wq, const float* __restrict__ bq,
    const float* __restrict__ Wk, const float* __restrict__ bk,
    const float* __restrict__ Wv, const float* __restrict__ bv)
{
    extern __shared__ float qsm[];
    float* As = qsm;                 // [128][68]
    float* Bs = qsm + 128 * 68;      // [64][68]

    const float* W; const float* bias; float* out;
    if      (blockIdx.z == 0) { W = Wq; bias = bq; out = g_Q; }
    else if (blockIdx.z == 1) { W = Wk; bias = bk; out = g_K; }
    else                      { W = Wv; bias = bv; out = g_V; }

    const int tid     = threadIdx.x;
    const int wid     = tid >> 5;
    const int lane    = tid & 31;
    const int g       = lane >> 2;
    const int tig     = lane & 3;
    const int wm      = (wid & 3) * 32;
    const int wn      = (wid >> 2) * 32;
    const int head    = blockIdx.x;
    const int mbase   = blockIdx.y * 128;
    const int colBase = head * 64;

    float acc[2][4][4];
    #pragma unroll
    for (int mt = 0; mt < 2; mt++)
        #pragma unroll
        for (int nt = 0; nt < 4; nt++)
            #pragma unroll
            for (int r = 0; r < 4; r++) acc[mt][nt][r] = 0.f;

    for (int c = 0; c < 12; c++) {
        __syncthreads();
        // stage A [128m][64k], tf32-rounded
        #pragma unroll
        for (int i = 0; i < 8; i++) {
            int f  = tid + i * 256;           // 0..2047 float4
            int m  = f >> 4;
            int k4 = (f & 15) * 4;
            float4 v = *(const float4*)&X[(size_t)(mbase + m) * HIDN + c * 64 + k4];
            v.x = to_tf32(v.x); v.y = to_tf32(v.y);
            v.z = to_tf32(v.z); v.w = to_tf32(v.w);
            *(float4*)&As[m * 68 + k4] = v;
        }
        // stage B [64k][64n], tf32-rounded
        #pragma unroll
        for (int i = 0; i < 4; i++) {
            int f  = tid + i * 256;           // 0..1023 float4
            int k  = f >> 4;
            int n4 = (f & 15) * 4;
            float4 v = *(const float4*)&W[(size_t)(c * 64 + k) * HIDN + colBase + n4];
            v.x = to_tf32(v.x); v.y = to_tf32(v.y);
            v.z = to_tf32(v.z); v.w = to_tf32(v.w);
            *(float4*)&Bs[k * 68 + n4] = v;
        }
        __syncthreads();

        #pragma unroll
        for (int ks = 0; ks < 8; ks++) {
            uint32_t a[2][4], b[4][2];
            #pragma unroll
            for (int mt = 0; mt < 2; mt++) {
                int r0 = wm + mt * 16 + g;
                a[mt][0] = __float_as_uint(As[(r0    ) * 68 + ks * 8 + tig    ]);
                a[mt][1] = __float_as_uint(As[(r0 + 8) * 68 + ks * 8 + tig    ]);
                a[mt][2] = __float_as_uint(As[(r0    ) * 68 + ks * 8 + tig + 4]);
                a[mt][3] = __float_as_uint(As[(r0 + 8) * 68 + ks * 8 + tig + 4]);
            }
            #pragma unroll
            for (int nt = 0; nt < 4; nt++) {
                int n = wn + nt * 8 + g;
                b[nt][0] = __float_as_uint(Bs[(ks * 8 + tig    ) * 68 + n]);
                b[nt][1] = __float_as_uint(Bs[(ks * 8 + tig + 4) * 68 + n]);
            }
            #pragma unroll
            for (int mt = 0; mt < 2; mt++)
                #pragma unroll
                for (int nt = 0; nt < 4; nt++)
                    mma_tf32(acc[mt][nt], a[mt], b[nt]);
        }
    }

    // epilogue: c0/c1 = row g cols 2tig/2tig+1; c2/c3 = row g+8
    #pragma unroll
    for (int mt = 0; mt < 2; mt++)
        #pragma unroll
        for (int rr = 0; rr < 2; rr++) {
            int m  = mbase + wm + mt * 16 + g + rr * 8;
            int bb = m >> 10, sr = m & 1023;
            #pragma unroll
            for (int nt = 0; nt < 4; nt++) {
                int d = wn + nt * 8 + 2 * tig;
                float2 o;
                o.x = acc[mt][nt][rr * 2 + 0] + bias[colBase + d];
                o.y = acc[mt][nt][rr * 2 + 1] + bias[colBase + d + 1];
                *(float2*)&out[(((size_t)bb * HH + head) * SS + sr) * DD + d] = o;
            }
        }
}

// ---------------------------------------------------------------------------
// Kernel 2: attention via mma.sync tf32 (core unchanged from R16 win;
// only the mask path now reads pre-packed g_mbits: 4KB/CTA contiguous).
// ---------------------------------------------------------------------------
#define AT_BUF   0
#define AT_KV0   32896
#define AT_KV1   (32896 + 8704)
#define AT_QS    50304
#define AT_AMS   52416
#define AT_EAM   53440
#define AT_GS    54464
#define AT_MB    54496
#define ATTN_SMEM_BYTES ((54496 + 1024) * 4)   // 222,080 B

__global__ __launch_bounds__(512, 1) void attn_mma(
    const float* __restrict__ am,     // [B,1,1,S]
    const float* __restrict__ gate,   // [B,H,S,1]
    float* __restrict__ out)          // [B,S,HID]
{
    extern __shared__ float smf[];
    float*    buf = smf + AT_BUF;
    float*    qs2 = smf + AT_QS;
    float*    ams = smf + AT_AMS;
    float*    eam = smf + AT_EAM;
    float*    gs  = smf + AT_GS;
    unsigned* mb  = (unsigned*)(smf + AT_MB);   // [32 q][32 kw]

    const int tid   = threadIdx.x;
    const int lane  = tid & 31;
    const int warp  = tid >> 5;
    const int g     = lane >> 2;
    const int tig   = lane & 3;
    const int qtile = blockIdx.x;
    const int h     = blockIdx.y;
    const int b     = blockIdx.z;
    const int qbase = qtile * 32;
    const size_t bh = (size_t)b * HH + h;
    const float* Qp = g_Q + bh * SS * DD;
    const float* Kp = g_K + bh * SS * DD;
    const float* Vp = g_V + bh * SS * DD;

    const int skey = tid >> 4;
    const int sdg  = (tid & 15) * 4;

    // ---- one-time staging ----
    #pragma unroll
    for (int i = 0; i < 4; i++) {
        int idx = tid + i * 512;
        int q = idx >> 6, d = idx & 63;
        qs2[q * 66 + d] = Qp[(size_t)(qbase + q) * DD + d];
    }
    if (tid < 256) {
        float4 v = *(const float4*)&am[(size_t)b * SS + tid * 4];
        *(float4*)&ams[tid * 4] = v;
    }
    if (tid < 32) gs[tid] = gate[bh * SS + qbase + tid];
    // mask bits: contiguous 1024-word copy (rows q of this tile)
    #pragma unroll
    for (int i = 0; i < 2; i++) {
        int w = tid + i * 512;
        mb[w] = g_mbits[((size_t)b * SS + qbase) * 32 + w];
    }
    __syncthreads();
    #pragma unroll
    for (int i = 0; i < 2; i++) {
        int k = tid + i * 512;
        eam[k] = __expf(-ams[k]);
    }

    // ---- Q -> A fragments in registers (tf32) ----
    const int wmq = (warp >> 3) * 16;
    uint32_t aQ[8][4];
    #pragma unroll
    for (int ks = 0; ks < 8; ks++) {
        aQ[ks][0] = __float_as_uint(to_tf32(qs2[(wmq + g    ) * 66 + ks * 8 + tig    ]));
        aQ[ks][1] = __float_as_uint(to_tf32(qs2[(wmq + g + 8) * 66 + ks * 8 + tig    ]));
        aQ[ks][2] = __float_as_uint(to_tf32(qs2[(wmq + g    ) * 66 + ks * 8 + tig + 4]));
        aQ[ks][3] = __float_as_uint(to_tf32(qs2[(wmq + g + 8) * 66 + ks * 8 + tig + 4]));
    }

    // ---- phase 1: scores = (Q K^T)/8, double-buffered K ----
    const int wnk = (warp & 7) * 16;
    {
        #pragma unroll
        for (int i = 0; i < 4; i++) {
            int key = skey + i * 32;
            float4 v = *(const float4*)&Kp[(size_t)key * DD + sdg];
            float* dst = smf + AT_KV0 + key * 68 + sdg;
            dst[0] = to_tf32(v.x); dst[1] = to_tf32(v.y);
            dst[2] = to_tf32(v.z); dst[3] = to_tf32(v.w);
        }
        __syncthreads();

        for (int c = 0; c < 8; c++) {
            const float* kvc = smf + ((c & 1) ? AT_KV1 : AT_KV0);
            float*       kvn = smf + ((c & 1) ? AT_KV0 : AT_KV1);

            float4 pre[4];
            if (c < 7) {
                #pragma unroll
                for (int i = 0; i < 4; i++) {
                    int key = skey + i * 32;
                    pre[i] = *(const float4*)&Kp[(size_t)((c + 1) * 128 + key) * DD + sdg];
                }
            }

            float accp[2][4];
            #pragma unroll
            for (int nt = 0; nt < 2; nt++)
                #pragma unroll
                for (int r = 0; r < 4; r++) accp[nt][r] = 0.f;

            #pragma unroll
            for (int ks = 0; ks < 8; ks++) {
                int d0 = ks * 8 + tig;
                uint32_t bf[2][2];
                #pragma unroll
                for (int nt = 0; nt < 2; nt++) {
                    int key = wnk + nt * 8 + g;
                    bf[nt][0] = __float_as_uint(kvc[key * 68 + d0    ]);
                    bf[nt][1] = __float_as_uint(kvc[key * 68 + d0 + 4]);
                }
                mma_tf32(accp[0], aQ[ks], bf[0]);
                mma_tf32(accp[1], aQ[ks], bf[1]);
            }
            #pragma unroll
            for (int nt = 0; nt < 2; nt++) {
                int kc = c * 128 + wnk + nt * 8 + 2 * tig;
                float2 lo = {accp[nt][0] * 0.125f, accp[nt][1] * 0.125f};
                float2 hi = {accp[nt][2] * 0.125f, accp[nt][3] * 0.125f};
                *(float2*)&buf[(wmq + g    ) * 1028 + kc] = lo;
                *(float2*)&buf[(wmq + g + 8) * 1028 + kc] = hi;
            }

            if (c < 7) {
                #pragma unroll
                for (int i = 0; i < 4; i++) {
                    int key = skey + i * 32;
                    float* dst = kvn + key * 68 + sdg;
                    dst[0] = to_tf32(pre[i].x); dst[1] = to_tf32(pre[i].y);
                    dst[2] = to_tf32(pre[i].z); dst[3] = to_tf32(pre[i].w);
                }
            }
            __syncthreads();
        }
    }

    // ---- phase 2: dual softmax + gate fold; weights stored tf32 ----
    #pragma unroll
    for (int i = 0; i < 2; i++) {
        int q = warp * 2 + i;
        float* row = buf + q * 1028;
        const unsigned* mbq = mb + q * 32;
        const int bb2 = (lane & 7) * 4;

        float4 eg[8];
        float zg = 0.f, zl = 0.f;
        #pragma unroll
        for (int kb = 0; kb < 8; kb++) {
            int k = kb * 128 + lane * 4;
            float4 s4 = *(const float4*)&row[k];
            float4 a4 = *(const float4*)&ams[k];
            float4 e4 = *(const float4*)&eam[k];
            unsigned mw = mbq[kb * 4 + (lane >> 3)];
            float4 e;
            e.x = __expf(s4.x + a4.x); e.y = __expf(s4.y + a4.y);
            e.z = __expf(s4.z + a4.z); e.w = __expf(s4.w + a4.w);
            eg[kb] = e;
            zg += (e.x + e.y) + (e.z + e.w);
            zl += (((mw >> (bb2 + 0)) & 1u) ? e.x * e4.x : 0.f)
                + (((mw >> (bb2 + 1)) & 1u) ? e.y * e4.y : 0.f)
                + (((mw >> (bb2 + 2)) & 1u) ? e.z * e4.z : 0.f)
                + (((mw >> (bb2 + 3)) & 1u) ? e.w * e4.w : 0.f);
        }
        #pragma unroll
        for (int o = 16; o; o >>= 1) {
            zg += __shfl_xor_sync(0xffffffffu, zg, o);
            zl += __shfl_xor_sync(0xffffffffu, zl, o);
        }
        float gg = gs[q];
        float cg = (1.f - gg) / zg;
        float cl = gg / zl;
        #pragma unroll
        for (int kb = 0; kb < 8; kb++) {
            int k = kb * 128 + lane * 4;
            float4 e4 = *(const float4*)&eam[k];
            unsigned mw = mbq[kb * 4 + (lane >> 3)];
            float4 w;
            w.x = to_tf32(eg[kb].x * (((mw >> (bb2 + 0)) & 1u) ? fmaf(cl, e4.x, cg) : cg));
            w.y = to_tf32(eg[kb].y * (((mw >> (bb2 + 1)) & 1u) ? fmaf(cl, e4.y, cg) : cg));
            w.z = to_tf32(eg[kb].z * (((mw >> (bb2 + 2)) & 1u) ? fmaf(cl, e4.z, cg) : cg));
            w.w = to_tf32(eg[kb].w * (((mw >> (bb2 + 3)) & 1u) ? fmaf(cl, e4.w, cg) : cg));
            *(float4*)&row[k] = w;
        }
    }

    // ---- phase 3: ctx = P @ V, double-buffered V ----
    const int wn3 = (warp & 7) * 8;
    float acc[4] = {0.f, 0.f, 0.f, 0.f};
    {
        #pragma unroll
        for (int i = 0; i < 4; i++) {
            int key = skey + i * 32;
            float4 v = *(const float4*)&Vp[(size_t)key * DD + sdg];
            float* dst = smf + AT_KV0 + key * 68 + sdg;
            dst[0] = to_tf32(v.x); dst[1] = to_tf32(v.y);
            dst[2] = to_tf32(v.z); dst[3] = to_tf32(v.w);
        }
        __syncthreads();

        for (int c = 0; c < 8; c++) {
            const float* kvc = smf + ((c & 1) ? AT_KV1 : AT_KV0);
            float*       kvn = smf + ((c & 1) ? AT_KV0 : AT_KV1);

            float4 pre[4];
            if (c < 7) {
                #pragma unroll
                for (int i = 0; i < 4; i++) {
                    int key = skey + i * 32;
                    pre[i] = *(const float4*)&Vp[(size_t)((c + 1) * 128 + key) * DD + sdg];
                }
            }

            const float* p0 = buf + (wmq + g    ) * 1028 + c * 128;
            const float* p1 = buf + (wmq + g + 8) * 1028 + c * 128;
            #pragma unroll 4
            for (int ks = 0; ks < 16; ks++) {
                int kk = ks * 8 + tig;
                uint32_t a[4], bb[2];
                a[0] = __float_as_uint(p0[kk    ]);
                a[1] = __float_as_uint(p1[kk    ]);
                a[2] = __float_as_uint(p0[kk + 4]);
                a[3] = __float_as_uint(p1[kk + 4]);
                bb[0] = __float_as_uint(kvc[(kk    ) * 68 + wn3 + g]);
                bb[1] = __float_as_uint(kvc[(kk + 4) * 68 + wn3 + g]);
                mma_tf32(acc, a, bb);
            }

            if (c < 7) {
                #pragma unroll
                for (int i = 0; i < 4; i++) {
                    int key = skey + i * 32;
                    float* dst = kvn + key * 68 + sdg;
                    dst[0] = to_tf32(pre[i].x); dst[1] = to_tf32(pre[i].y);
                    dst[2] = to_tf32(pre[i].z); dst[3] = to_tf32(pre[i].w);
                }
            }
            __syncthreads();
        }
    }

    // ---- epilogue ----
    {
        int q0   = qbase + wmq + g;
        int dcol = h * DD + wn3 + 2 * tig;
        float2 o0 = {acc[0], acc[1]};
        float2 o1 = {acc[2], acc[3]};
        *(float2*)&out[((size_t)b * SS + q0    ) * HIDN + dcol] = o0;
        *(float2*)&out[((size_t)b * SS + q0 + 8) * HIDN + dcol] = o1;
    }
}

// ---------------------------------------------------------------------------
// Launch: three kernels on the capture stream. No sync, no allocation.
// ---------------------------------------------------------------------------
extern "C" void kernel_launch(void* const* d_in, const int* in_sizes, int n_in,
                              void* d_out, int out_size)
{
    const float* hs   = (const float*)d_in[0];
    const float* am   = (const float*)d_in[1];
    const int*   lmsk = (const int*)  d_in[2];
    const float* gate = (const float*)d_in[3];
    const float* Wq   = (const float*)d_in[4];
    const float* bq   = (const float*)d_in[5];
    const float* Wk   = (const float*)d_in[6];
    const float* bk   = (const float*)d_in[7];
    const float* Wv   = (const float*)d_in[8];
    const float* bv   = (const float*)d_in[9];
    float* out = (float*)d_out;

    cudaFuncSetAttribute(qkv_mma,
                         cudaFuncAttributeMaxDynamicSharedMemorySize,
                         QKV_SMEM_BYTES);
    cudaFuncSetAttribute(attn_mma,
                         cudaFuncAttributeMaxDynamicSharedMemorySize,
                         ATTN_SMEM_BYTES);

    pack_mask<<<512, 256>>>(lmsk);      // 4096 warps = 4096 (b,q) rows

    dim3 gm(12, 32, 3);                 // heads x m-tiles x {Q,K,V}
    qkv_mma<<<gm, 256, QKV_SMEM_BYTES>>>(hs, Wq, bq, Wk, bk, Wv, bv);

    dim3 ga(32, 12, 4);                 // q-tiles x heads x batch
    attn_mma<<<ga, 512, ATTN_SMEM_BYTES>>>(am, gate, out);
}